// round 1
// baseline (speedup 1.0000x reference)
#include <cuda_runtime.h>

// Problem constants (fixed shapes for this problem instance)
constexpr int N  = 20000;   // nodes
constexpr int K  = 16;      // eigenvector slots
constexpr int E  = 160000;  // edges
constexpr int G  = 100;     // graphs
constexpr int H  = 64;      // hidden / C_OUT
constexpr int ROWS = N * K; // 320000
constexpr int NODES_PER_BLK = 4;
constexpr int BLKS = N / NODES_PER_BLK; // 5000

// -------- scratch (device globals; no allocations allowed) --------
__device__ __align__(16) float g_h0[ROWS * H];   // per-sign layer activations
__device__ __align__(16) float g_h1[ROWS * H];
__device__ __align__(16) float g_acc[N * H];     // masked-K sum, accumulated over signs
__device__ int g_deg[N];
__device__ int g_rowptr[N + 1];
__device__ int g_cursor[N];
__device__ int g_cols[E];
__device__ int g_gcnt[G];

// -------- CSR build --------
__global__ void init_kernel() {
    int i = blockIdx.x * blockDim.x + threadIdx.x;
    if (i < N) g_deg[i] = 0;
    if (i < G) g_gcnt[i] = 0;
}

__global__ void count_kernel(const int* __restrict__ ei, const int* __restrict__ batch) {
    int i = blockIdx.x * blockDim.x + threadIdx.x;
    int stride = gridDim.x * blockDim.x;
    for (int t = i; t < E + N; t += stride) {
        if (t < E) atomicAdd(&g_deg[ei[E + t]], 1);          // in-degree by dst
        else       atomicAdd(&g_gcnt[batch[t - E]], 1);      // nodes per graph
    }
}

__global__ void scan_kernel() {
    __shared__ int part[1024];
    int tid = threadIdx.x;
    const int CH = (N + 1023) / 1024;  // 20
    int base = tid * CH;
    int s = 0;
    for (int q = 0; q < CH; q++) { int idx = base + q; if (idx < N) s += g_deg[idx]; }
    part[tid] = s;
    __syncthreads();
    for (int off = 1; off < 1024; off <<= 1) {
        int v = (tid >= off) ? part[tid - off] : 0;
        __syncthreads();
        part[tid] += v;
        __syncthreads();
    }
    int run = (tid == 0) ? 0 : part[tid - 1];
    for (int q = 0; q < CH; q++) {
        int idx = base + q;
        if (idx < N) { g_rowptr[idx] = run; g_cursor[idx] = run; run += g_deg[idx]; }
    }
    if (tid == 1023) g_rowptr[N] = run;
}

__global__ void fill_kernel(const int* __restrict__ ei) {
    int i = blockIdx.x * blockDim.x + threadIdx.x;
    int stride = gridDim.x * blockDim.x;
    for (int e = i; e < E; e += stride) {
        int dst = ei[E + e];
        int pos = atomicAdd(&g_cursor[dst], 1);
        g_cols[pos] = ei[e];  // src
    }
}

// -------- register-tiled 64x64x64 smem GEMM (4x4 tile per thread) --------
__device__ __forceinline__ void gemm64(const float* __restrict__ sA,
                                       const float* __restrict__ sB,
                                       int r0, int c0, float acc[4][4]) {
#pragma unroll
    for (int i = 0; i < 4; i++)
#pragma unroll
        for (int j = 0; j < 4; j++) acc[i][j] = 0.f;
#pragma unroll 4
    for (int k = 0; k < 64; k++) {
        float a0 = sA[(r0 + 0) * 64 + k];
        float a1 = sA[(r0 + 1) * 64 + k];
        float a2 = sA[(r0 + 2) * 64 + k];
        float a3 = sA[(r0 + 3) * 64 + k];
        float4 w = *reinterpret_cast<const float4*>(sB + k * 64 + c0);
        acc[0][0] += a0 * w.x; acc[0][1] += a0 * w.y; acc[0][2] += a0 * w.z; acc[0][3] += a0 * w.w;
        acc[1][0] += a1 * w.x; acc[1][1] += a1 * w.y; acc[1][2] += a1 * w.z; acc[1][3] += a1 * w.w;
        acc[2][0] += a2 * w.x; acc[2][1] += a2 * w.y; acc[2][2] += a2 * w.z; acc[2][3] += a2 * w.w;
        acc[3][0] += a3 * w.x; acc[3][1] += a3 * w.y; acc[3][2] += a3 * w.z; acc[3][3] += a3 * w.w;
    }
}

// -------- layer 0: x (C_IN=1) -> g_h0, with sign --------
__global__ __launch_bounds__(256) void layer0_kernel(
    const float* __restrict__ x,
    const float* __restrict__ W1, const float* __restrict__ b1,
    const float* __restrict__ W2, const float* __restrict__ b2,
    float sign) {
    __shared__ float sS[64 * 64];
    __shared__ float sW[64 * 64];
    __shared__ float sk[64];
    int tid = threadIdx.x;
    int base = blockIdx.x * NODES_PER_BLK;

    for (int i = tid; i < 4096; i += 256) sW[i] = W2[i];
    if (tid < 64) {
        int nl = tid >> 4, k = tid & 15;
        int i = base + nl;
        float s = x[i * K + k];
        int rp = g_rowptr[i], re = g_rowptr[i + 1];
        for (int e = rp; e < re; e++) s += x[g_cols[e] * K + k];
        sk[tid] = s * sign;
    }
    __syncthreads();

    int r0 = (tid >> 4) << 2, c0 = (tid & 15) << 2;
    float4 w1  = *reinterpret_cast<const float4*>(W1 + c0);
    float4 bb1 = *reinterpret_cast<const float4*>(b1 + c0);
#pragma unroll
    for (int i = 0; i < 4; i++) {
        float sv = sk[r0 + i];
        float4 t;
        t.x = fmaxf(sv * w1.x + bb1.x, 0.f);
        t.y = fmaxf(sv * w1.y + bb1.y, 0.f);
        t.z = fmaxf(sv * w1.z + bb1.z, 0.f);
        t.w = fmaxf(sv * w1.w + bb1.w, 0.f);
        *reinterpret_cast<float4*>(sS + (r0 + i) * 64 + c0) = t;
    }
    __syncthreads();

    float acc[4][4];
    gemm64(sS, sW, r0, c0, acc);
    float4 bb2 = *reinterpret_cast<const float4*>(b2 + c0);
#pragma unroll
    for (int i = 0; i < 4; i++) {
        int row = base * K + r0 + i;
        float4 o = { acc[i][0] + bb2.x, acc[i][1] + bb2.y,
                     acc[i][2] + bb2.z, acc[i][3] + bb2.w };
        *reinterpret_cast<float4*>(g_h0 + row * 64 + c0) = o;
    }
}

// -------- layers 1/2: fused CSR gather + 2-GEMM MLP --------
// MODE 0: g_h0 -> g_h1.  MODE 1: g_h1 -> g_acc (masked-K reduce, += over signs)
template <int MODE>
__global__ __launch_bounds__(256) void layer_kernel(
    const float* __restrict__ W1, const float* __restrict__ b1,
    const float* __restrict__ W2, const float* __restrict__ b2,
    const int* __restrict__ batch, int accumulate) {
    __shared__ float sS[64 * 64];
    __shared__ float sW[64 * 64];
    __shared__ float sRed[256];
    int tid = threadIdx.x;
    int base = blockIdx.x * NODES_PER_BLK;
    const float* __restrict__ hin = (MODE == 0) ? g_h0 : g_h1;

    for (int i = tid; i < 4096; i += 256) sW[i] = W1[i];
    {   // gather: 64 threads per node, float4-vectorized; s = h_i + sum_{j->i} h_j
        int nl = tid >> 6, t64 = tid & 63;
        int i = base + nl;
        const float4* h4 = reinterpret_cast<const float4*>(hin);
        float4 a[4];
#pragma unroll
        for (int q = 0; q < 4; q++) a[q] = h4[i * 256 + q * 64 + t64];
        int rp = g_rowptr[i], re = g_rowptr[i + 1];
        for (int e = rp; e < re; e++) {
            const float4* hj = h4 + g_cols[e] * 256;
#pragma unroll
            for (int q = 0; q < 4; q++) {
                float4 v = hj[q * 64 + t64];
                a[q].x += v.x; a[q].y += v.y; a[q].z += v.z; a[q].w += v.w;
            }
        }
        float4* s4 = reinterpret_cast<float4*>(sS);
#pragma unroll
        for (int q = 0; q < 4; q++) s4[nl * 256 + q * 64 + t64] = a[q];
    }
    __syncthreads();

    int r0 = (tid >> 4) << 2, c0 = (tid & 15) << 2;
    float acc[4][4];
    gemm64(sS, sW, r0, c0, acc);     // GEMM1
    __syncthreads();                 // all reads of sS done before overwrite

    float4 bb1 = *reinterpret_cast<const float4*>(b1 + c0);
#pragma unroll
    for (int i = 0; i < 4; i++) {    // t = relu(s@W1+b1) back into sS
        float4 t = { fmaxf(acc[i][0] + bb1.x, 0.f), fmaxf(acc[i][1] + bb1.y, 0.f),
                     fmaxf(acc[i][2] + bb1.z, 0.f), fmaxf(acc[i][3] + bb1.w, 0.f) };
        *reinterpret_cast<float4*>(sS + (r0 + i) * 64 + c0) = t;
    }
    for (int i = tid; i < 4096; i += 256) sW[i] = W2[i];
    if (MODE == 1) sRed[tid] = 0.f;
    __syncthreads();

    gemm64(sS, sW, r0, c0, acc);     // GEMM2
    float4 bb2 = *reinterpret_cast<const float4*>(b2 + c0);

    if (MODE == 0) {
#pragma unroll
        for (int i = 0; i < 4; i++) {
            int row = base * K + r0 + i;
            float4 o = { acc[i][0] + bb2.x, acc[i][1] + bb2.y,
                         acc[i][2] + bb2.z, acc[i][3] + bb2.w };
            *reinterpret_cast<float4*>(g_h1 + row * 64 + c0) = o;
        }
    } else {
        // masked reduction over k (k < n_nodes of node's graph), then acc over signs
        int nl = r0 >> 4, k0 = r0 & 15;
        int i = base + nl;
        int nn = g_gcnt[batch[i]];
        float p0 = 0.f, p1 = 0.f, p2 = 0.f, p3 = 0.f;
#pragma unroll
        for (int r = 0; r < 4; r++) {
            if (k0 + r < nn) {
                p0 += acc[r][0] + bb2.x;
                p1 += acc[r][1] + bb2.y;
                p2 += acc[r][2] + bb2.z;
                p3 += acc[r][3] + bb2.w;
            }
        }
        atomicAdd(&sRed[nl * 64 + c0 + 0], p0);
        atomicAdd(&sRed[nl * 64 + c0 + 1], p1);
        atomicAdd(&sRed[nl * 64 + c0 + 2], p2);
        atomicAdd(&sRed[nl * 64 + c0 + 3], p3);
        __syncthreads();
        int nl2 = tid >> 6, c = tid & 63;
        float v = sRed[tid];
        float* dp = g_acc + (base + nl2) * 64 + c;
        if (accumulate) *dp += v; else *dp = v;
    }
}

// -------- rho MLP: g_acc [N,64] -> out [N,16] --------
__global__ __launch_bounds__(256) void rho_kernel(
    const float* __restrict__ rW1, const float* __restrict__ rb1,
    const float* __restrict__ rW2, const float* __restrict__ rb2,
    float* __restrict__ out) {
    __shared__ float v[4][64];
    __shared__ float t[4][64];
    int tid = threadIdx.x;
    int nl = tid >> 6, c = tid & 63;
    int i = blockIdx.x * 4 + nl;
    v[nl][c] = g_acc[i * 64 + c];
    __syncthreads();
    float s = rb1[c];
#pragma unroll 4
    for (int k = 0; k < 64; k++) s += v[nl][k] * rW1[k * 64 + c];
    t[nl][c] = fmaxf(s, 0.f);
    __syncthreads();
    if (c < 16) {
        float o = rb2[c];
#pragma unroll 4
        for (int k = 0; k < 64; k++) o += t[nl][k] * rW2[k * 16 + c];
        out[i * 16 + c] = o;
    }
}

// -------- launch --------
extern "C" void kernel_launch(void* const* d_in, const int* in_sizes, int n_in,
                              void* d_out, int out_size) {
    (void)in_sizes; (void)n_in; (void)out_size;
    const float* x     = (const float*)d_in[0];
    const int*   ei    = (const int*)d_in[1];
    const int*   batch = (const int*)d_in[2];
    const float* gW1[3] = {(const float*)d_in[3], (const float*)d_in[7],  (const float*)d_in[11]};
    const float* gb1[3] = {(const float*)d_in[4], (const float*)d_in[8],  (const float*)d_in[12]};
    const float* gW2[3] = {(const float*)d_in[5], (const float*)d_in[9],  (const float*)d_in[13]};
    const float* gb2[3] = {(const float*)d_in[6], (const float*)d_in[10], (const float*)d_in[14]};
    const float* rW1 = (const float*)d_in[15];
    const float* rb1 = (const float*)d_in[16];
    const float* rW2 = (const float*)d_in[17];
    const float* rb2 = (const float*)d_in[18];

    init_kernel<<<(N + 255) / 256, 256>>>();
    count_kernel<<<160, 256>>>(ei, batch);
    scan_kernel<<<1, 1024>>>();
    fill_kernel<<<160, 256>>>(ei);

    for (int sgn = 0; sgn < 2; sgn++) {
        float sv = sgn ? -1.f : 1.f;
        layer0_kernel<<<BLKS, 256>>>(x, gW1[0], gb1[0], gW2[0], gb2[0], sv);
        layer_kernel<0><<<BLKS, 256>>>(gW1[1], gb1[1], gW2[1], gb2[1], nullptr, 0);
        layer_kernel<1><<<BLKS, 256>>>(gW1[2], gb1[2], gW2[2], gb2[2], batch, sgn);
    }
    rho_kernel<<<BLKS, 256>>>(rW1, rb1, rW2, rb2, (float*)d_out);
}

// round 5
// speedup vs baseline: 1.7394x; 1.7394x over previous
#include <cuda_runtime.h>
#include <cstdint>

// Problem constants
constexpr int N  = 20000;
constexpr int K  = 16;
constexpr int E  = 160000;
constexpr int G  = 100;
constexpr int NODES_PER_BLK = 4;          // 4 nodes * 16 k = 64 MMA rows per CTA
constexpr int BLKS = N / NODES_PER_BLK;   // 5000
constexpr int SROW = 68;                  // padded smem row stride (floats)

// -------- scratch (device globals; no allocations allowed) --------
__device__ __align__(16) float g_h0[(size_t)N * K * 64];
__device__ __align__(16) float g_h1[(size_t)N * K * 64];
__device__ __align__(16) float g_acc[(size_t)N * 64];
__device__ int g_deg[N];
__device__ int g_rowptr[N + 1];
__device__ int g_cursor[N];
__device__ int g_cols[E];
__device__ int g_gcnt[G];

// ================= helpers =================
__device__ __forceinline__ float tf32r(float a) {
    uint32_t u; asm("cvt.rna.tf32.f32 %0, %1;" : "=r"(u) : "f"(a));
    return __uint_as_float(u);
}

__device__ __forceinline__ void mma8(float d[4], uint32_t a0, uint32_t a1,
                                     uint32_t a2, uint32_t a3,
                                     uint32_t b0, uint32_t b1) {
    asm volatile(
        "mma.sync.aligned.m16n8k8.row.col.f32.tf32.tf32.f32 "
        "{%0,%1,%2,%3}, {%4,%5,%6,%7}, {%8,%9}, {%0,%1,%2,%3};"
        : "+f"(d[0]), "+f"(d[1]), "+f"(d[2]), "+f"(d[3])
        : "r"(a0), "r"(a1), "r"(a2), "r"(a3), "r"(b0), "r"(b1));
}

// 64x64x64 GEMM on tensor cores. Warp w owns rows r0..r0+15, cols cb..cb+31.
// acc[nt][0..3] = D fragment for n-tile nt.
__device__ __forceinline__ void gemm_mma(const float* __restrict__ sS,
                                         const float* __restrict__ sW,
                                         int r0, int cb, int l, float acc[4][4]) {
#pragma unroll
    for (int nt = 0; nt < 4; nt++)
#pragma unroll
        for (int j = 0; j < 4; j++) acc[nt][j] = 0.f;
    int ar = r0 + (l >> 2);
    int ac = l & 3;
    int nr = l >> 2;
#pragma unroll
    for (int ks = 0; ks < 8; ks++) {
        int k0 = ks * 8;
        uint32_t a0 = __float_as_uint(sS[ar * SROW + k0 + ac]);
        uint32_t a1 = __float_as_uint(sS[(ar + 8) * SROW + k0 + ac]);
        uint32_t a2 = __float_as_uint(sS[ar * SROW + k0 + ac + 4]);
        uint32_t a3 = __float_as_uint(sS[(ar + 8) * SROW + k0 + ac + 4]);
#pragma unroll
        for (int nt = 0; nt < 4; nt++) {
            int n0 = cb + nt * 8 + nr;
            uint32_t b0 = __float_as_uint(sW[(k0 + ac) * SROW + n0]);
            uint32_t b1 = __float_as_uint(sW[(k0 + ac + 4) * SROW + n0]);
            mma8(acc[nt], a0, a1, a2, a3, b0, b1);
        }
    }
}

// -------- CSR build --------
__global__ void init_kernel() {
    int i = blockIdx.x * blockDim.x + threadIdx.x;
    if (i < N) g_deg[i] = 0;
    if (i < G) g_gcnt[i] = 0;
}
__global__ void count_kernel(const int* __restrict__ ei, const int* __restrict__ batch) {
    int i = blockIdx.x * blockDim.x + threadIdx.x;
    int stride = gridDim.x * blockDim.x;
    for (int t = i; t < E + N; t += stride) {
        if (t < E) atomicAdd(&g_deg[ei[E + t]], 1);
        else       atomicAdd(&g_gcnt[batch[t - E]], 1);
    }
}
__global__ void scan_kernel() {
    __shared__ int part[1024];
    int tid = threadIdx.x;
    const int CH = (N + 1023) / 1024;
    int base = tid * CH;
    int s = 0;
    for (int q = 0; q < CH; q++) { int idx = base + q; if (idx < N) s += g_deg[idx]; }
    part[tid] = s;
    __syncthreads();
    for (int off = 1; off < 1024; off <<= 1) {
        int v = (tid >= off) ? part[tid - off] : 0;
        __syncthreads();
        part[tid] += v;
        __syncthreads();
    }
    int run = (tid == 0) ? 0 : part[tid - 1];
    for (int q = 0; q < CH; q++) {
        int idx = base + q;
        if (idx < N) { g_rowptr[idx] = run; g_cursor[idx] = run; run += g_deg[idx]; }
    }
    if (tid == 1023) g_rowptr[N] = run;
}
__global__ void fill_kernel(const int* __restrict__ ei) {
    int i = blockIdx.x * blockDim.x + threadIdx.x;
    int stride = gridDim.x * blockDim.x;
    for (int e = i; e < E; e += stride) {
        int dst = ei[E + e];
        int pos = atomicAdd(&g_cursor[dst], 1);
        g_cols[pos] = ei[e];
    }
}

// ================= fused layer kernel (tf32 mma.sync) =================
// MODE 0: x -> g_h0 (rank-1 W1 + relu, then tensor GEMM with W2), sign applied
// MODE 1: g_h0 -> g_h1 (gather + W1 + relu + W2)
// MODE 2: g_h1 -> g_acc (gather + W1 + relu + W2 + masked-K reduce; += if accumulate)
template <int MODE>
__global__ __launch_bounds__(256) void layer_mma(
    const float* __restrict__ x,
    const float* __restrict__ W1, const float* __restrict__ b1,
    const float* __restrict__ W2, const float* __restrict__ b2,
    const int* __restrict__ batch, int accumulate, float sign)
{
    __shared__ float sS[64 * SROW];
    __shared__ float sW[64 * SROW];
    __shared__ float sk[64];

    int tid = threadIdx.x, w = tid >> 5, l = tid & 31;
    int base = blockIdx.x * NODES_PER_BLK;
    int r0 = (w >> 1) * 16, cb = (w & 1) * 32;

    // ---- stage first-GEMM weight (rounded to tf32) ----
    const float* WB = (MODE == 0) ? W2 : W1;
    for (int e = tid; e < 4096; e += 256) {
        int k = e >> 6, n = e & 63;
        sW[k * SROW + n] = tf32r(WB[e]);
    }

    // ---- build A tile ----
    if (MODE == 0) {
        if (tid < 64) {
            int i = base + (tid >> 4);
            int k = tid & 15;
            float s = x[i * K + k];
            int rp = g_rowptr[i], re = g_rowptr[i + 1];
            for (int e = rp; e < re; e++) s += x[g_cols[e] * K + k];
            sk[tid] = s * sign;
        }
        __syncthreads();
        // sS[row][c] = tf32(relu(sk[row]*W1[c] + b1[c])); 4 threads per row, 16 cols each
        int row = tid >> 2, c0 = (tid & 3) * 16;
        float sv = sk[row];
#pragma unroll
        for (int q = 0; q < 4; q++) {
            float4 wv = __ldg((const float4*)(W1 + c0) + q);
            float4 bv = __ldg((const float4*)(b1 + c0) + q);
            float4 t;
            t.x = tf32r(fmaxf(fmaf(sv, wv.x, bv.x), 0.f));
            t.y = tf32r(fmaxf(fmaf(sv, wv.y, bv.y), 0.f));
            t.z = tf32r(fmaxf(fmaf(sv, wv.z, bv.z), 0.f));
            t.w = tf32r(fmaxf(fmaf(sv, wv.w, bv.w), 0.f));
            *(float4*)(sS + row * SROW + c0 + q * 4) = t;
        }
    } else {
        // gather: 64 threads per node, float4-vectorized
        int nl = tid >> 6, t64 = tid & 63;
        int i = base + nl;
        const float4* h4 = (const float4*)((MODE == 1) ? g_h0 : g_h1);
        float4 a[4];
#pragma unroll
        for (int q = 0; q < 4; q++) a[q] = h4[(size_t)i * 256 + q * 64 + t64];
        int rp = g_rowptr[i], re = g_rowptr[i + 1];
        for (int e = rp; e < re; e++) {
            const float4* hj = h4 + (size_t)g_cols[e] * 256;
#pragma unroll
            for (int q = 0; q < 4; q++) {
                float4 v = hj[q * 64 + t64];
                a[q].x += v.x; a[q].y += v.y; a[q].z += v.z; a[q].w += v.w;
            }
        }
#pragma unroll
        for (int q = 0; q < 4; q++) {
            int f = q * 64 + t64;
            int row = nl * 16 + (f >> 4), c4 = (f & 15) * 4;
            float4 t;
            t.x = tf32r(a[q].x); t.y = tf32r(a[q].y);
            t.z = tf32r(a[q].z); t.w = tf32r(a[q].w);
            *(float4*)(sS + row * SROW + c4) = t;
        }
    }
    __syncthreads();

    // ---- GEMM1 ----
    float acc[4][4];
    gemm_mma(sS, sW, r0, cb, l, acc);

    if (MODE == 0) {
        // epilogue: D + b2 -> g_h0
        int R = blockIdx.x * 64 + r0 + (l >> 2);
#pragma unroll
        for (int nt = 0; nt < 4; nt++) {
            int col = cb + nt * 8 + 2 * (l & 3);
            float2 bv = __ldg((const float2*)(b2 + col));
            float2 v0 = { acc[nt][0] + bv.x, acc[nt][1] + bv.y };
            float2 v1 = { acc[nt][2] + bv.x, acc[nt][3] + bv.y };
            *(float2*)(g_h0 + (size_t)R * 64 + col) = v0;
            *(float2*)(g_h0 + (size_t)(R + 8) * 64 + col) = v1;
        }
        return;
    }

    __syncthreads();   // all GEMM1 smem reads complete

    // t = tf32(relu(D1 + b1)) back into sS; restage sW = W2
    {
        int rd = r0 + (l >> 2);
#pragma unroll
        for (int nt = 0; nt < 4; nt++) {
            int col = cb + nt * 8 + 2 * (l & 3);
            float2 bv = __ldg((const float2*)(b1 + col));
            float2 v0 = { tf32r(fmaxf(acc[nt][0] + bv.x, 0.f)),
                          tf32r(fmaxf(acc[nt][1] + bv.y, 0.f)) };
            float2 v1 = { tf32r(fmaxf(acc[nt][2] + bv.x, 0.f)),
                          tf32r(fmaxf(acc[nt][3] + bv.y, 0.f)) };
            *(float2*)(sS + rd * SROW + col) = v0;
            *(float2*)(sS + (rd + 8) * SROW + col) = v1;
        }
    }
    for (int e = tid; e < 4096; e += 256) {
        int k = e >> 6, n = e & 63;
        sW[k * SROW + n] = tf32r(W2[e]);
    }
    __syncthreads();

    // ---- GEMM2 ----
    gemm_mma(sS, sW, r0, cb, l, acc);

    if (MODE == 1) {
        int R = blockIdx.x * 64 + r0 + (l >> 2);
#pragma unroll
        for (int nt = 0; nt < 4; nt++) {
            int col = cb + nt * 8 + 2 * (l & 3);
            float2 bv = __ldg((const float2*)(b2 + col));
            float2 v0 = { acc[nt][0] + bv.x, acc[nt][1] + bv.y };
            float2 v1 = { acc[nt][2] + bv.x, acc[nt][3] + bv.y };
            *(float2*)(g_h1 + (size_t)R * 64 + col) = v0;
            *(float2*)(g_h1 + (size_t)(R + 8) * 64 + col) = v1;
        }
    } else {
        // MODE 2: stage D2 + b2 into sS, masked reduce over k, accumulate g_acc
        __syncthreads();   // all GEMM2 smem reads complete before overwrite
        {
            int rd = r0 + (l >> 2);
#pragma unroll
            for (int nt = 0; nt < 4; nt++) {
                int col = cb + nt * 8 + 2 * (l & 3);
                float2 bv = __ldg((const float2*)(b2 + col));
                float2 v0 = { acc[nt][0] + bv.x, acc[nt][1] + bv.y };
                float2 v1 = { acc[nt][2] + bv.x, acc[nt][3] + bv.y };
                *(float2*)(sS + rd * SROW + col) = v0;
                *(float2*)(sS + (rd + 8) * SROW + col) = v1;
            }
        }
        __syncthreads();
        int nl = tid >> 6, c = tid & 63;
        int i2 = base + nl;
        int nn = g_gcnt[batch[i2]];
        if (nn > 16) nn = 16;
        float s = 0.f;
        for (int k2 = 0; k2 < nn; k2++) s += sS[(nl * 16 + k2) * SROW + c];
        float* dp = g_acc + (size_t)i2 * 64 + c;
        if (accumulate) *dp += s; else *dp = s;
    }
}

// -------- rho MLP: g_acc [N,64] -> out [N,16] --------
__global__ __launch_bounds__(256) void rho_kernel(
    const float* __restrict__ rW1, const float* __restrict__ rb1,
    const float* __restrict__ rW2, const float* __restrict__ rb2,
    float* __restrict__ out) {
    __shared__ float v[4][64];
    __shared__ float t[4][64];
    int tid = threadIdx.x;
    int nl = tid >> 6, c = tid & 63;
    int i = blockIdx.x * 4 + nl;
    v[nl][c] = g_acc[(size_t)i * 64 + c];
    __syncthreads();
    float s = rb1[c];
#pragma unroll 4
    for (int k = 0; k < 64; k++) s += v[nl][k] * rW1[k * 64 + c];
    t[nl][c] = fmaxf(s, 0.f);
    __syncthreads();
    if (c < 16) {
        float o = rb2[c];
#pragma unroll 4
        for (int k = 0; k < 64; k++) o += t[nl][k] * rW2[k * 16 + c];
        out[i * 16 + c] = o;
    }
}

// -------- launch --------
extern "C" void kernel_launch(void* const* d_in, const int* in_sizes, int n_in,
                              void* d_out, int out_size) {
    (void)in_sizes; (void)n_in; (void)out_size;
    const float* x     = (const float*)d_in[0];
    const int*   ei    = (const int*)d_in[1];
    const int*   batch = (const int*)d_in[2];
    const float* gW1[3] = {(const float*)d_in[3], (const float*)d_in[7],  (const float*)d_in[11]};
    const float* gb1[3] = {(const float*)d_in[4], (const float*)d_in[8],  (const float*)d_in[12]};
    const float* gW2[3] = {(const float*)d_in[5], (const float*)d_in[9],  (const float*)d_in[13]};
    const float* gb2[3] = {(const float*)d_in[6], (const float*)d_in[10], (const float*)d_in[14]};
    const float* rW1 = (const float*)d_in[15];
    const float* rb1 = (const float*)d_in[16];
    const float* rW2 = (const float*)d_in[17];
    const float* rb2 = (const float*)d_in[18];

    init_kernel<<<(N + 255) / 256, 256>>>();
    count_kernel<<<160, 256>>>(ei, batch);
    scan_kernel<<<1, 1024>>>();
    fill_kernel<<<160, 256>>>(ei);

    for (int sgn = 0; sgn < 2; sgn++) {
        float sv = sgn ? -1.f : 1.f;
        layer_mma<0><<<BLKS, 256>>>(x, gW1[0], gb1[0], gW2[0], gb2[0], nullptr, 0, sv);
        layer_mma<1><<<BLKS, 256>>>(x, gW1[1], gb1[1], gW2[1], gb2[1], nullptr, 0, 1.f);
        layer_mma<2><<<BLKS, 256>>>(x, gW1[2], gb1[2], gW2[2], gb2[2], batch, sgn, 1.f);
    }
    rho_kernel<<<N / 4, 256>>>(rW1, rb1, rW2, rb2, (float*)d_out);
}

// round 6
// speedup vs baseline: 2.0664x; 1.1880x over previous
#include <cuda_runtime.h>
#include <cstdint>

// Problem constants
constexpr int N  = 20000;
constexpr int K  = 16;
constexpr int E  = 160000;
constexpr int G  = 100;
constexpr int NPB  = 4;            // nodes per block (x2 signs x16 k = 128 MMA rows)
constexpr int BLKS = N / NPB;      // 5000
constexpr int AS = 68;             // sS row stride (floats) — A-frag conflict-free
constexpr int WS = 72;             // sW row stride (floats) — B-frag conflict-free

// h layout: [node][sign][k][c] -> ((node*2+sign)*16+k)*64+c ; 1024 floats per (node,sign)
__device__ __align__(16) float g_h0[(size_t)N * 2 * 1024];
__device__ __align__(16) float g_h1[(size_t)N * 2 * 1024];
__device__ __align__(16) float g_acc[(size_t)N * 64];
__device__ int g_deg[N];
__device__ int g_rowptr[N + 1];
__device__ int g_cursor[N];
__device__ int g_cols[E];
__device__ int g_gcnt[G];

// ================= helpers =================
__device__ __forceinline__ float tf32r(float a) {
    uint32_t u; asm("cvt.rna.tf32.f32 %0, %1;" : "=r"(u) : "f"(a));
    return __uint_as_float(u);
}

__device__ __forceinline__ void mma8(float d[4], uint32_t a0, uint32_t a1,
                                     uint32_t a2, uint32_t a3,
                                     uint32_t b0, uint32_t b1) {
    asm volatile(
        "mma.sync.aligned.m16n8k8.row.col.f32.tf32.tf32.f32 "
        "{%0,%1,%2,%3}, {%4,%5,%6,%7}, {%8,%9}, {%0,%1,%2,%3};"
        : "+f"(d[0]), "+f"(d[1]), "+f"(d[2]), "+f"(d[3])
        : "r"(a0), "r"(a1), "r"(a2), "r"(a3), "r"(b0), "r"(b1));
}

// Warp GEMM: rows r0..r0+15 (M=16), cols 0..63 (8 n-tiles), K=64.
__device__ __forceinline__ void gemm_mma(const float* __restrict__ sS,
                                         const float* __restrict__ sW,
                                         int r0, int l, float acc[8][4]) {
#pragma unroll
    for (int nt = 0; nt < 8; nt++)
#pragma unroll
        for (int j = 0; j < 4; j++) acc[nt][j] = 0.f;
    int ar = r0 + (l >> 2);
    int ac = l & 3;
    int nr = l >> 2;
#pragma unroll
    for (int ks = 0; ks < 8; ks++) {
        int k0 = ks * 8;
        uint32_t a0 = __float_as_uint(sS[ar * AS + k0 + ac]);
        uint32_t a1 = __float_as_uint(sS[(ar + 8) * AS + k0 + ac]);
        uint32_t a2 = __float_as_uint(sS[ar * AS + k0 + ac + 4]);
        uint32_t a3 = __float_as_uint(sS[(ar + 8) * AS + k0 + ac + 4]);
#pragma unroll
        for (int nt = 0; nt < 8; nt++) {
            int n0 = nt * 8 + nr;
            uint32_t b0 = __float_as_uint(sW[(k0 + ac) * WS + n0]);
            uint32_t b1 = __float_as_uint(sW[(k0 + ac + 4) * WS + n0]);
            mma8(acc[nt], a0, a1, a2, a3, b0, b1);
        }
    }
}

__device__ __forceinline__ void stage_w(float* sW, const float* __restrict__ W, int tid) {
    for (int e = tid; e < 1024; e += 256) {
        int k = e >> 4, n4 = (e & 15) * 4;
        float4 v = __ldg((const float4*)(W + k * 64 + n4));
        v.x = tf32r(v.x); v.y = tf32r(v.y); v.z = tf32r(v.z); v.w = tf32r(v.w);
        *(float4*)(sW + k * WS + n4) = v;
    }
}

// -------- CSR build --------
__global__ void init_kernel() {
    int i = blockIdx.x * blockDim.x + threadIdx.x;
    if (i < N) g_deg[i] = 0;
    if (i < G) g_gcnt[i] = 0;
}
__global__ void count_kernel(const int* __restrict__ ei, const int* __restrict__ batch) {
    int i = blockIdx.x * blockDim.x + threadIdx.x;
    int stride = gridDim.x * blockDim.x;
    for (int t = i; t < E + N; t += stride) {
        if (t < E) atomicAdd(&g_deg[ei[E + t]], 1);
        else       atomicAdd(&g_gcnt[batch[t - E]], 1);
    }
}
__global__ void scan_kernel() {
    __shared__ int part[1024];
    int tid = threadIdx.x;
    const int CH = (N + 1023) / 1024;
    int base = tid * CH;
    int s = 0;
    for (int q = 0; q < CH; q++) { int idx = base + q; if (idx < N) s += g_deg[idx]; }
    part[tid] = s;
    __syncthreads();
    for (int off = 1; off < 1024; off <<= 1) {
        int v = (tid >= off) ? part[tid - off] : 0;
        __syncthreads();
        part[tid] += v;
        __syncthreads();
    }
    int run = (tid == 0) ? 0 : part[tid - 1];
    for (int q = 0; q < CH; q++) {
        int idx = base + q;
        if (idx < N) { g_rowptr[idx] = run; g_cursor[idx] = run; run += g_deg[idx]; }
    }
    if (tid == 1023) g_rowptr[N] = run;
}
__global__ void fill_kernel(const int* __restrict__ ei) {
    int i = blockIdx.x * blockDim.x + threadIdx.x;
    int stride = gridDim.x * blockDim.x;
    for (int e = i; e < E; e += stride) {
        int dst = ei[E + e];
        int pos = atomicAdd(&g_cursor[dst], 1);
        g_cols[pos] = ei[e];
    }
}

// ================= fused layer kernel (both signs per CTA) =================
// MODE 0: x -> g_h0            (rank-1 W1 + relu, tensor GEMM with W2; both signs)
// MODE 1: g_h0 -> g_h1         (gather + W1 + relu + W2; both signs)
// MODE 2: g_h1 -> g_acc        (gather + MLP + masked-K reduce over k AND signs)
// A rows: r = (nl*2 + sign)*16 + k,  nl in [0,4), 128 rows.
// Warp w <-> (nl = w>>1, sign = w&1) owns rows w*16..w*16+15.
template <int MODE>
__global__ __launch_bounds__(256, 4) void layer_mma(
    const float* __restrict__ x,
    const float* __restrict__ W1, const float* __restrict__ b1,
    const float* __restrict__ W2, const float* __restrict__ b2,
    const int* __restrict__ batch)
{
    extern __shared__ float dyn[];
    float* sS = dyn;                    // 128 * AS
    float* sW = dyn + 128 * AS;         // 64 * WS
    float* sk = sW + 64 * WS;           // 64

    int tid = threadIdx.x, w = tid >> 5, l = tid & 31;
    int base = blockIdx.x * NPB;

    stage_w(sW, (MODE == 0) ? W2 : W1, tid);

    if (MODE == 0) {
        if (tid < 64) {
            int nl = tid >> 4, k = tid & 15;
            int i = base + nl;
            float s = x[i * K + k];
            int rp = g_rowptr[i], re = g_rowptr[i + 1];
            for (int e = rp; e < re; e++) s += x[g_cols[e] * K + k];
            sk[tid] = s;
        }
        __syncthreads();
        // A[r][c] = tf32(relu(+/-s * W1[c] + b1[c])); 2 threads per row, 32 cols each
        int r = tid >> 1, c0 = (tid & 1) * 32;
        int nl = r >> 5, sgn = (r >> 4) & 1, k = r & 15;
        float sv = sk[nl * 16 + k];
        if (sgn) sv = -sv;
#pragma unroll
        for (int q = 0; q < 8; q++) {
            float4 wv = __ldg((const float4*)(W1 + c0) + q);
            float4 bv = __ldg((const float4*)(b1 + c0) + q);
            float4 t;
            t.x = tf32r(fmaxf(fmaf(sv, wv.x, bv.x), 0.f));
            t.y = tf32r(fmaxf(fmaf(sv, wv.y, bv.y), 0.f));
            t.z = tf32r(fmaxf(fmaf(sv, wv.z, bv.z), 0.f));
            t.w = tf32r(fmaxf(fmaf(sv, wv.w, bv.w), 0.f));
            *(float4*)(sS + r * AS + c0 + q * 4) = t;
        }
    } else {
        // gather: warp w -> (node, sign); edge loop unrolled x2 for MLP
        int i = base + (w >> 1), sgn = w & 1;
        const float4* h4 = (const float4*)((MODE == 1) ? g_h0 : g_h1);
        const float4* self = h4 + ((size_t)i * 2 + sgn) * 256;
        float4 a[8];
#pragma unroll
        for (int q = 0; q < 8; q++) a[q] = self[l + 32 * q];
        int rp = g_rowptr[i], re = g_rowptr[i + 1];
        int e = rp;
        for (; e + 1 < re; e += 2) {
            const float4* p0 = h4 + ((size_t)g_cols[e]     * 2 + sgn) * 256;
            const float4* p1 = h4 + ((size_t)g_cols[e + 1] * 2 + sgn) * 256;
#pragma unroll
            for (int q = 0; q < 8; q++) {
                float4 v0 = p0[l + 32 * q];
                float4 v1 = p1[l + 32 * q];
                a[q].x += v0.x + v1.x; a[q].y += v0.y + v1.y;
                a[q].z += v0.z + v1.z; a[q].w += v0.w + v1.w;
            }
        }
        if (e < re) {
            const float4* p0 = h4 + ((size_t)g_cols[e] * 2 + sgn) * 256;
#pragma unroll
            for (int q = 0; q < 8; q++) {
                float4 v0 = p0[l + 32 * q];
                a[q].x += v0.x; a[q].y += v0.y; a[q].z += v0.z; a[q].w += v0.w;
            }
        }
#pragma unroll
        for (int q = 0; q < 8; q++) {
            int f = l + 32 * q;
            int k = f >> 4, c4 = (f & 15) * 4;
            float4 t;
            t.x = tf32r(a[q].x); t.y = tf32r(a[q].y);
            t.z = tf32r(a[q].z); t.w = tf32r(a[q].w);
            *(float4*)(sS + (w * 16 + k) * AS + c4) = t;
        }
    }
    __syncthreads();

    // ---- GEMM1 ----
    float acc[8][4];
    int r0 = w * 16;
    gemm_mma(sS, sW, r0, l, acc);

    if (MODE == 0) {
        size_t gb = ((size_t)(base + (w >> 1)) * 2 + (w & 1)) * 1024;
        int k = l >> 2;
#pragma unroll
        for (int nt = 0; nt < 8; nt++) {
            int col = nt * 8 + 2 * (l & 3);
            float2 bv = __ldg((const float2*)(b2 + col));
            float2 v0 = { acc[nt][0] + bv.x, acc[nt][1] + bv.y };
            float2 v1 = { acc[nt][2] + bv.x, acc[nt][3] + bv.y };
            *(float2*)(g_h0 + gb + (size_t)k * 64 + col) = v0;
            *(float2*)(g_h0 + gb + (size_t)(k + 8) * 64 + col) = v1;
        }
        return;
    }

    __syncthreads();   // all GEMM1 smem reads complete

    // t = tf32(relu(D1 + b1)) back into sS; restage sW = W2
    {
        int rd = r0 + (l >> 2);
#pragma unroll
        for (int nt = 0; nt < 8; nt++) {
            int col = nt * 8 + 2 * (l & 3);
            float2 bv = __ldg((const float2*)(b1 + col));
            float2 v0 = { tf32r(fmaxf(acc[nt][0] + bv.x, 0.f)),
                          tf32r(fmaxf(acc[nt][1] + bv.y, 0.f)) };
            float2 v1 = { tf32r(fmaxf(acc[nt][2] + bv.x, 0.f)),
                          tf32r(fmaxf(acc[nt][3] + bv.y, 0.f)) };
            *(float2*)(sS + rd * AS + col) = v0;
            *(float2*)(sS + (rd + 8) * AS + col) = v1;
        }
    }
    stage_w(sW, W2, tid);
    __syncthreads();

    // ---- GEMM2 ----
    gemm_mma(sS, sW, r0, l, acc);

    if (MODE == 1) {
        size_t gb = ((size_t)(base + (w >> 1)) * 2 + (w & 1)) * 1024;
        int k = l >> 2;
#pragma unroll
        for (int nt = 0; nt < 8; nt++) {
            int col = nt * 8 + 2 * (l & 3);
            float2 bv = __ldg((const float2*)(b2 + col));
            float2 v0 = { acc[nt][0] + bv.x, acc[nt][1] + bv.y };
            float2 v1 = { acc[nt][2] + bv.x, acc[nt][3] + bv.y };
            *(float2*)(g_h1 + gb + (size_t)k * 64 + col) = v0;
            *(float2*)(g_h1 + gb + (size_t)(k + 8) * 64 + col) = v1;
        }
    } else {
        // MODE 2: stage D2 + b2 into sS; masked reduce over signs and k; store g_acc
        __syncthreads();   // all GEMM2 smem reads complete before overwrite
        {
            int rd = r0 + (l >> 2);
#pragma unroll
            for (int nt = 0; nt < 8; nt++) {
                int col = nt * 8 + 2 * (l & 3);
                float2 bv = __ldg((const float2*)(b2 + col));
                float2 v0 = { acc[nt][0] + bv.x, acc[nt][1] + bv.y };
                float2 v1 = { acc[nt][2] + bv.x, acc[nt][3] + bv.y };
                *(float2*)(sS + rd * AS + col) = v0;
                *(float2*)(sS + (rd + 8) * AS + col) = v1;
            }
        }
        __syncthreads();
        int nl = tid >> 6, c = tid & 63;
        int i2 = base + nl;
        int nn = g_gcnt[batch[i2]];
        if (nn > 16) nn = 16;
        float s = 0.f;
#pragma unroll 2
        for (int sg = 0; sg < 2; sg++)
            for (int k2 = 0; k2 < nn; k2++)
                s += sS[((nl * 2 + sg) * 16 + k2) * AS + c];
        g_acc[(size_t)i2 * 64 + c] = s;
    }
}

// -------- rho MLP: g_acc [N,64] -> out [N,16] --------
__global__ __launch_bounds__(256) void rho_kernel(
    const float* __restrict__ rW1, const float* __restrict__ rb1,
    const float* __restrict__ rW2, const float* __restrict__ rb2,
    float* __restrict__ out) {
    __shared__ float v[4][64];
    __shared__ float t[4][64];
    int tid = threadIdx.x;
    int nl = tid >> 6, c = tid & 63;
    int i = blockIdx.x * 4 + nl;
    v[nl][c] = g_acc[(size_t)i * 64 + c];
    __syncthreads();
    float s = rb1[c];
#pragma unroll 4
    for (int k = 0; k < 64; k++) s += v[nl][k] * rW1[k * 64 + c];
    t[nl][c] = fmaxf(s, 0.f);
    __syncthreads();
    if (c < 16) {
        float o = rb2[c];
#pragma unroll 4
        for (int k = 0; k < 64; k++) o += t[nl][k] * rW2[k * 16 + c];
        out[i * 16 + c] = o;
    }
}

// -------- launch --------
extern "C" void kernel_launch(void* const* d_in, const int* in_sizes, int n_in,
                              void* d_out, int out_size) {
    (void)in_sizes; (void)n_in; (void)out_size;
    const float* x     = (const float*)d_in[0];
    const int*   ei    = (const int*)d_in[1];
    const int*   batch = (const int*)d_in[2];
    const float* gW1[3] = {(const float*)d_in[3], (const float*)d_in[7],  (const float*)d_in[11]};
    const float* gb1[3] = {(const float*)d_in[4], (const float*)d_in[8],  (const float*)d_in[12]};
    const float* gW2[3] = {(const float*)d_in[5], (const float*)d_in[9],  (const float*)d_in[13]};
    const float* gb2[3] = {(const float*)d_in[6], (const float*)d_in[10], (const float*)d_in[14]};
    const float* rW1 = (const float*)d_in[15];
    const float* rb1 = (const float*)d_in[16];
    const float* rW2 = (const float*)d_in[17];
    const float* rb2 = (const float*)d_in[18];

    const int SMEMSZ = (128 * AS + 64 * WS + 64) * 4;   // 53504 bytes
    static bool attr_done = false;
    if (!attr_done) {
        cudaFuncSetAttribute(layer_mma<0>, cudaFuncAttributeMaxDynamicSharedMemorySize, SMEMSZ);
        cudaFuncSetAttribute(layer_mma<1>, cudaFuncAttributeMaxDynamicSharedMemorySize, SMEMSZ);
        cudaFuncSetAttribute(layer_mma<2>, cudaFuncAttributeMaxDynamicSharedMemorySize, SMEMSZ);
        attr_done = true;
    }

    init_kernel<<<(N + 255) / 256, 256>>>();
    count_kernel<<<160, 256>>>(ei, batch);
    scan_kernel<<<1, 1024>>>();
    fill_kernel<<<160, 256>>>(ei);

    layer_mma<0><<<BLKS, 256, SMEMSZ>>>(x, gW1[0], gb1[0], gW2[0], gb2[0], batch);
    layer_mma<1><<<BLKS, 256, SMEMSZ>>>(x, gW1[1], gb1[1], gW2[1], gb2[1], batch);
    layer_mma<2><<<BLKS, 256, SMEMSZ>>>(x, gW1[2], gb1[2], gW2[2], gb2[2], batch);

    rho_kernel<<<N / 4, 256>>>(rW1, rb1, rW2, rb2, (float*)d_out);
}

// round 7
// speedup vs baseline: 2.1412x; 1.0362x over previous
#include <cuda_runtime.h>
#include <cstdint>

// Problem constants
constexpr int N  = 20000;
constexpr int K  = 16;
constexpr int E  = 160000;
constexpr int G  = 100;
constexpr int NPB  = 8;            // nodes per block (x2 signs x16 k = 256 MMA rows)
constexpr int BLKS = N / NPB;      // 2500
constexpr int NT   = 512;          // threads per CTA (16 warps)
constexpr int AS = 68;             // sS row stride (floats) — A-frag conflict-free
constexpr int WS = 72;             // sW row stride (floats) — B-frag conflict-free

// h layout: [node][sign][k][c] -> ((node*2+sign)*16+k)*64+c ; 1024 floats per (node,sign)
__device__ __align__(16) float g_h0[(size_t)N * 2 * 1024];
__device__ __align__(16) float g_h1[(size_t)N * 2 * 1024];
__device__ __align__(16) float g_acc[(size_t)N * 64];
__device__ int g_deg[N];
__device__ int g_rowptr[N + 1];
__device__ int g_cursor[N];
__device__ int g_cols[E];
__device__ int g_gcnt[G];

// ================= helpers =================
__device__ __forceinline__ float tf32r(float a) {
    uint32_t u; asm("cvt.rna.tf32.f32 %0, %1;" : "=r"(u) : "f"(a));
    return __uint_as_float(u);
}

__device__ __forceinline__ void mma8(float d[4], uint32_t a0, uint32_t a1,
                                     uint32_t a2, uint32_t a3,
                                     uint32_t b0, uint32_t b1) {
    asm volatile(
        "mma.sync.aligned.m16n8k8.row.col.f32.tf32.tf32.f32 "
        "{%0,%1,%2,%3}, {%4,%5,%6,%7}, {%8,%9}, {%0,%1,%2,%3};"
        : "+f"(d[0]), "+f"(d[1]), "+f"(d[2]), "+f"(d[3])
        : "r"(a0), "r"(a1), "r"(a2), "r"(a3), "r"(b0), "r"(b1));
}

// Warp GEMM: rows r0..r0+15 (M=16), cols 0..63 (8 n-tiles), K=64.
__device__ __forceinline__ void gemm_mma(const float* __restrict__ sS,
                                         const float* __restrict__ sW,
                                         int r0, int l, float acc[8][4]) {
#pragma unroll
    for (int nt = 0; nt < 8; nt++)
#pragma unroll
        for (int j = 0; j < 4; j++) acc[nt][j] = 0.f;
    int ar = r0 + (l >> 2);
    int ac = l & 3;
    int nr = l >> 2;
#pragma unroll
    for (int ks = 0; ks < 8; ks++) {
        int k0 = ks * 8;
        uint32_t a0 = __float_as_uint(sS[ar * AS + k0 + ac]);
        uint32_t a1 = __float_as_uint(sS[(ar + 8) * AS + k0 + ac]);
        uint32_t a2 = __float_as_uint(sS[ar * AS + k0 + ac + 4]);
        uint32_t a3 = __float_as_uint(sS[(ar + 8) * AS + k0 + ac + 4]);
#pragma unroll
        for (int nt = 0; nt < 8; nt++) {
            int n0 = nt * 8 + nr;
            uint32_t b0 = __float_as_uint(sW[(k0 + ac) * WS + n0]);
            uint32_t b1 = __float_as_uint(sW[(k0 + ac + 4) * WS + n0]);
            mma8(acc[nt], a0, a1, a2, a3, b0, b1);
        }
    }
}

__device__ __forceinline__ void stage_w(float* sW, const float* __restrict__ W, int tid) {
    for (int e = tid; e < 1024; e += NT) {
        int k = e >> 4, n4 = (e & 15) * 4;
        float4 v = __ldg((const float4*)(W + k * 64 + n4));
        v.x = tf32r(v.x); v.y = tf32r(v.y); v.z = tf32r(v.z); v.w = tf32r(v.w);
        *(float4*)(sW + k * WS + n4) = v;
    }
}

// -------- CSR build --------
__global__ void init_kernel() {
    int i = blockIdx.x * blockDim.x + threadIdx.x;
    if (i < N) g_deg[i] = 0;
    if (i < G) g_gcnt[i] = 0;
}
__global__ void count_kernel(const int* __restrict__ ei, const int* __restrict__ batch) {
    int i = blockIdx.x * blockDim.x + threadIdx.x;
    int stride = gridDim.x * blockDim.x;
    for (int t = i; t < E + N; t += stride) {
        if (t < E) atomicAdd(&g_deg[ei[E + t]], 1);
        else       atomicAdd(&g_gcnt[batch[t - E]], 1);
    }
}
__global__ void scan_kernel() {
    __shared__ int part[1024];
    int tid = threadIdx.x;
    const int CH = (N + 1023) / 1024;
    int base = tid * CH;
    int s = 0;
    for (int q = 0; q < CH; q++) { int idx = base + q; if (idx < N) s += g_deg[idx]; }
    part[tid] = s;
    __syncthreads();
    for (int off = 1; off < 1024; off <<= 1) {
        int v = (tid >= off) ? part[tid - off] : 0;
        __syncthreads();
        part[tid] += v;
        __syncthreads();
    }
    int run = (tid == 0) ? 0 : part[tid - 1];
    for (int q = 0; q < CH; q++) {
        int idx = base + q;
        if (idx < N) { g_rowptr[idx] = run; g_cursor[idx] = run; run += g_deg[idx]; }
    }
    if (tid == 1023) g_rowptr[N] = run;
}
__global__ void fill_kernel(const int* __restrict__ ei) {
    int i = blockIdx.x * blockDim.x + threadIdx.x;
    int stride = gridDim.x * blockDim.x;
    for (int e = i; e < E; e += stride) {
        int dst = ei[E + e];
        int pos = atomicAdd(&g_cursor[dst], 1);
        g_cols[pos] = ei[e];
    }
}

// ================= fused layer kernel (both signs per CTA, 8 nodes) =================
// MODE 0: x -> g_h0            (rank-1 W1 + relu, tensor GEMM with W2; both signs)
// MODE 1: g_h0 -> g_h1         (gather + W1 + relu + W2; both signs)
// MODE 2: g_h1 -> g_acc        (gather + MLP + masked-K reduce over k AND signs)
// A rows: r = (nl*2 + sign)*16 + k,  nl in [0,8), 256 rows.
// Warp w <-> (nl = w>>1, sign = w&1) owns rows w*16..w*16+15.
template <int MODE>
__global__ __launch_bounds__(NT, 2) void layer_mma(
    const float* __restrict__ x,
    const float* __restrict__ W1, const float* __restrict__ b1,
    const float* __restrict__ W2, const float* __restrict__ b2,
    const int* __restrict__ batch)
{
    extern __shared__ float dyn[];
    float* sS = dyn;                    // 256 * AS
    float* sW = dyn + 256 * AS;         // 64 * WS
    float* sk = sW + 64 * WS;           // 128

    int tid = threadIdx.x, w = tid >> 5, l = tid & 31;
    int base = blockIdx.x * NPB;

    stage_w(sW, (MODE == 0) ? W2 : W1, tid);

    if (MODE == 0) {
        if (tid < 128) {
            int nl = tid >> 4, k = tid & 15;
            int i = base + nl;
            float s = x[i * K + k];
            int rp = g_rowptr[i], re = g_rowptr[i + 1];
            for (int e = rp; e < re; e++) s += x[g_cols[e] * K + k];
            sk[tid] = s;
        }
        __syncthreads();
        // A[r][c] = tf32(relu(+/-s * W1[c] + b1[c])); 2 threads per row, 32 cols each
        int r = tid >> 1, c0 = (tid & 1) * 32;
        int nl = r >> 5, sgn = (r >> 4) & 1, k = r & 15;
        float sv = sk[nl * 16 + k];
        if (sgn) sv = -sv;
#pragma unroll
        for (int q = 0; q < 8; q++) {
            float4 wv = __ldg((const float4*)(W1 + c0) + q);
            float4 bv = __ldg((const float4*)(b1 + c0) + q);
            float4 t;
            t.x = tf32r(fmaxf(fmaf(sv, wv.x, bv.x), 0.f));
            t.y = tf32r(fmaxf(fmaf(sv, wv.y, bv.y), 0.f));
            t.z = tf32r(fmaxf(fmaf(sv, wv.z, bv.z), 0.f));
            t.w = tf32r(fmaxf(fmaf(sv, wv.w, bv.w), 0.f));
            *(float4*)(sS + r * AS + c0 + q * 4) = t;
        }
    } else {
        // gather: warp w -> (node, sign); edge loop unrolled x2
        int i = base + (w >> 1), sgn = w & 1;
        const float4* h4 = (const float4*)((MODE == 1) ? g_h0 : g_h1);
        const float4* self = h4 + ((size_t)i * 2 + sgn) * 256;
        float4 a[8];
#pragma unroll
        for (int q = 0; q < 8; q++) a[q] = self[l + 32 * q];
        int rp = g_rowptr[i], re = g_rowptr[i + 1];
        int e = rp;
        for (; e + 1 < re; e += 2) {
            const float4* p0 = h4 + ((size_t)g_cols[e]     * 2 + sgn) * 256;
            const float4* p1 = h4 + ((size_t)g_cols[e + 1] * 2 + sgn) * 256;
#pragma unroll
            for (int q = 0; q < 8; q++) {
                float4 v0 = p0[l + 32 * q];
                float4 v1 = p1[l + 32 * q];
                a[q].x += v0.x + v1.x; a[q].y += v0.y + v1.y;
                a[q].z += v0.z + v1.z; a[q].w += v0.w + v1.w;
            }
        }
        if (e < re) {
            const float4* p0 = h4 + ((size_t)g_cols[e] * 2 + sgn) * 256;
#pragma unroll
            for (int q = 0; q < 8; q++) {
                float4 v0 = p0[l + 32 * q];
                a[q].x += v0.x; a[q].y += v0.y; a[q].z += v0.z; a[q].w += v0.w;
            }
        }
#pragma unroll
        for (int q = 0; q < 8; q++) {
            int f = l + 32 * q;
            int k = f >> 4, c4 = (f & 15) * 4;
            float4 t;
            t.x = tf32r(a[q].x); t.y = tf32r(a[q].y);
            t.z = tf32r(a[q].z); t.w = tf32r(a[q].w);
            *(float4*)(sS + (w * 16 + k) * AS + c4) = t;
        }
    }
    __syncthreads();

    // ---- GEMM1 ----
    float acc[8][4];
    int r0 = w * 16;
    gemm_mma(sS, sW, r0, l, acc);

    if (MODE == 0) {
        size_t gb = ((size_t)(base + (w >> 1)) * 2 + (w & 1)) * 1024;
        int k = l >> 2;
#pragma unroll
        for (int nt = 0; nt < 8; nt++) {
            int col = nt * 8 + 2 * (l & 3);
            float2 bv = __ldg((const float2*)(b2 + col));
            float2 v0 = { acc[nt][0] + bv.x, acc[nt][1] + bv.y };
            float2 v1 = { acc[nt][2] + bv.x, acc[nt][3] + bv.y };
            *(float2*)(g_h0 + gb + (size_t)k * 64 + col) = v0;
            *(float2*)(g_h0 + gb + (size_t)(k + 8) * 64 + col) = v1;
        }
        return;
    }

    __syncthreads();   // all GEMM1 smem reads complete

    // t = tf32(relu(D1 + b1)) back into sS; restage sW = W2
    {
        int rd = r0 + (l >> 2);
#pragma unroll
        for (int nt = 0; nt < 8; nt++) {
            int col = nt * 8 + 2 * (l & 3);
            float2 bv = __ldg((const float2*)(b1 + col));
            float2 v0 = { tf32r(fmaxf(acc[nt][0] + bv.x, 0.f)),
                          tf32r(fmaxf(acc[nt][1] + bv.y, 0.f)) };
            float2 v1 = { tf32r(fmaxf(acc[nt][2] + bv.x, 0.f)),
                          tf32r(fmaxf(acc[nt][3] + bv.y, 0.f)) };
            *(float2*)(sS + rd * AS + col) = v0;
            *(float2*)(sS + (rd + 8) * AS + col) = v1;
        }
    }
    stage_w(sW, W2, tid);
    __syncthreads();

    // ---- GEMM2 ----
    gemm_mma(sS, sW, r0, l, acc);

    if (MODE == 1) {
        size_t gb = ((size_t)(base + (w >> 1)) * 2 + (w & 1)) * 1024;
        int k = l >> 2;
#pragma unroll
        for (int nt = 0; nt < 8; nt++) {
            int col = nt * 8 + 2 * (l & 3);
            float2 bv = __ldg((const float2*)(b2 + col));
            float2 v0 = { acc[nt][0] + bv.x, acc[nt][1] + bv.y };
            float2 v1 = { acc[nt][2] + bv.x, acc[nt][3] + bv.y };
            *(float2*)(g_h1 + gb + (size_t)k * 64 + col) = v0;
            *(float2*)(g_h1 + gb + (size_t)(k + 8) * 64 + col) = v1;
        }
    } else {
        // MODE 2: stage D2 + b2 into sS; masked reduce over signs and k; store g_acc
        __syncthreads();   // all GEMM2 smem reads complete before overwrite
        {
            int rd = r0 + (l >> 2);
#pragma unroll
            for (int nt = 0; nt < 8; nt++) {
                int col = nt * 8 + 2 * (l & 3);
                float2 bv = __ldg((const float2*)(b2 + col));
                float2 v0 = { acc[nt][0] + bv.x, acc[nt][1] + bv.y };
                float2 v1 = { acc[nt][2] + bv.x, acc[nt][3] + bv.y };
                *(float2*)(sS + rd * AS + col) = v0;
                *(float2*)(sS + (rd + 8) * AS + col) = v1;
            }
        }
        __syncthreads();
        int nl = tid >> 6, c = tid & 63;   // 8 nodes x 64 channels
        int i2 = base + nl;
        int nn = g_gcnt[batch[i2]];
        if (nn > 16) nn = 16;
        float s = 0.f;
#pragma unroll 2
        for (int sg = 0; sg < 2; sg++)
            for (int k2 = 0; k2 < nn; k2++)
                s += sS[((nl * 2 + sg) * 16 + k2) * AS + c];
        g_acc[(size_t)i2 * 64 + c] = s;
    }
}

// -------- rho MLP: g_acc [N,64] -> out [N,16] --------
__global__ __launch_bounds__(256) void rho_kernel(
    const float* __restrict__ rW1, const float* __restrict__ rb1,
    const float* __restrict__ rW2, const float* __restrict__ rb2,
    float* __restrict__ out) {
    __shared__ float v[4][64];
    __shared__ float t[4][64];
    int tid = threadIdx.x;
    int nl = tid >> 6, c = tid & 63;
    int i = blockIdx.x * 4 + nl;
    v[nl][c] = g_acc[(size_t)i * 64 + c];
    __syncthreads();
    float s = rb1[c];
#pragma unroll 4
    for (int k = 0; k < 64; k++) s += v[nl][k] * rW1[k * 64 + c];
    t[nl][c] = fmaxf(s, 0.f);
    __syncthreads();
    if (c < 16) {
        float o = rb2[c];
#pragma unroll 4
        for (int k = 0; k < 64; k++) o += t[nl][k] * rW2[k * 16 + c];
        out[i * 16 + c] = o;
    }
}

// -------- launch --------
extern "C" void kernel_launch(void* const* d_in, const int* in_sizes, int n_in,
                              void* d_out, int out_size) {
    (void)in_sizes; (void)n_in; (void)out_size;
    const float* x     = (const float*)d_in[0];
    const int*   ei    = (const int*)d_in[1];
    const int*   batch = (const int*)d_in[2];
    const float* gW1[3] = {(const float*)d_in[3], (const float*)d_in[7],  (const float*)d_in[11]};
    const float* gb1[3] = {(const float*)d_in[4], (const float*)d_in[8],  (const float*)d_in[12]};
    const float* gW2[3] = {(const float*)d_in[5], (const float*)d_in[9],  (const float*)d_in[13]};
    const float* gb2[3] = {(const float*)d_in[6], (const float*)d_in[10], (const float*)d_in[14]};
    const float* rW1 = (const float*)d_in[15];
    const float* rb1 = (const float*)d_in[16];
    const float* rW2 = (const float*)d_in[17];
    const float* rb2 = (const float*)d_in[18];

    const int SMEMSZ = (256 * AS + 64 * WS + 128) * 4;   // 88576 bytes
    static bool attr_done = false;
    if (!attr_done) {
        cudaFuncSetAttribute(layer_mma<0>, cudaFuncAttributeMaxDynamicSharedMemorySize, SMEMSZ);
        cudaFuncSetAttribute(layer_mma<1>, cudaFuncAttributeMaxDynamicSharedMemorySize, SMEMSZ);
        cudaFuncSetAttribute(layer_mma<2>, cudaFuncAttributeMaxDynamicSharedMemorySize, SMEMSZ);
        attr_done = true;
    }

    init_kernel<<<(N + 255) / 256, 256>>>();
    count_kernel<<<160, 256>>>(ei, batch);
    scan_kernel<<<1, 1024>>>();
    fill_kernel<<<160, 256>>>(ei);

    layer_mma<0><<<BLKS, NT, SMEMSZ>>>(x, gW1[0], gb1[0], gW2[0], gb2[0], batch);
    layer_mma<1><<<BLKS, NT, SMEMSZ>>>(x, gW1[1], gb1[1], gW2[1], gb2[1], batch);
    layer_mma<2><<<BLKS, NT, SMEMSZ>>>(x, gW1[2], gb1[2], gW2[2], gb2[2], batch);

    rho_kernel<<<N / 4, 256>>>(rW1, rb1, rW2, rb2, (float*)d_out);
}

// round 11
// speedup vs baseline: 2.9585x; 1.3817x over previous
#include <cuda_runtime.h>
#include <cuda_fp16.h>
#include <cstdint>

// Problem constants
constexpr int N  = 20000;
constexpr int K  = 16;
constexpr int E  = 160000;
constexpr int G  = 100;
constexpr int NPB  = 8;            // nodes per block (x2 signs x16 k = 256 MMA rows)
constexpr int BLKS = N / NPB;      // 2500
constexpr int NT   = 512;          // threads per CTA (16 warps)
constexpr int AS = 68;             // sS row stride (floats) — A-frag conflict-free
constexpr int WS = 72;             // sW row stride (floats) — B-frag conflict-free

// h layout: [node][sign][k][c] -> ((node*2+sign)*16+k)*64+c ; 1024 halves per (node,sign)
__device__ __align__(16) __half g_h0[(size_t)N * 2 * 1024];
__device__ __align__(16) __half g_h1[(size_t)N * 2 * 1024];
__device__ __align__(16) float  g_acc[(size_t)N * 64];
__device__ int g_deg[N];
__device__ int g_rowptr[N + 1];
__device__ int g_cursor[N];
__device__ int g_cols[E];
__device__ int g_gcnt[G];

// ================= helpers =================
__device__ __forceinline__ float tf32r(float a) {
    uint32_t u; asm("cvt.rna.tf32.f32 %0, %1;" : "=r"(u) : "f"(a));
    return __uint_as_float(u);
}

__device__ __forceinline__ void mma8(float d[4], uint32_t a0, uint32_t a1,
                                     uint32_t a2, uint32_t a3,
                                     uint32_t b0, uint32_t b1) {
    asm volatile(
        "mma.sync.aligned.m16n8k8.row.col.f32.tf32.tf32.f32 "
        "{%0,%1,%2,%3}, {%4,%5,%6,%7}, {%8,%9}, {%0,%1,%2,%3};"
        : "+f"(d[0]), "+f"(d[1]), "+f"(d[2]), "+f"(d[3])
        : "r"(a0), "r"(a1), "r"(a2), "r"(a3), "r"(b0), "r"(b1));
}

// Warp GEMM: rows r0..r0+15 (M=16), cols 0..63 (8 n-tiles), K=64.
__device__ __forceinline__ void gemm_mma(const float* __restrict__ sS,
                                         const float* __restrict__ sW,
                                         int r0, int l, float acc[8][4]) {
#pragma unroll
    for (int nt = 0; nt < 8; nt++)
#pragma unroll
        for (int j = 0; j < 4; j++) acc[nt][j] = 0.f;
    int ar = r0 + (l >> 2);
    int ac = l & 3;
    int nr = l >> 2;
#pragma unroll
    for (int ks = 0; ks < 8; ks++) {
        int k0 = ks * 8;
        uint32_t a0 = __float_as_uint(sS[ar * AS + k0 + ac]);
        uint32_t a1 = __float_as_uint(sS[(ar + 8) * AS + k0 + ac]);
        uint32_t a2 = __float_as_uint(sS[ar * AS + k0 + ac + 4]);
        uint32_t a3 = __float_as_uint(sS[(ar + 8) * AS + k0 + ac + 4]);
#pragma unroll
        for (int nt = 0; nt < 8; nt++) {
            int n0 = nt * 8 + nr;
            uint32_t b0 = __float_as_uint(sW[(k0 + ac) * WS + n0]);
            uint32_t b1 = __float_as_uint(sW[(k0 + ac + 4) * WS + n0]);
            mma8(acc[nt], a0, a1, a2, a3, b0, b1);
        }
    }
}

__device__ __forceinline__ void stage_w(float* sW, const float* __restrict__ W, int tid) {
    for (int e = tid; e < 1024; e += NT) {
        int k = e >> 4, n4 = (e & 15) * 4;
        float4 v = __ldg((const float4*)(W + k * 64 + n4));
        v.x = tf32r(v.x); v.y = tf32r(v.y); v.z = tf32r(v.z); v.w = tf32r(v.w);
        *(float4*)(sW + k * WS + n4) = v;
    }
}

// accumulate one uint4 (8 halves) into 4 float2 accumulators
__device__ __forceinline__ void acc8(float2* a, uint4 v) {
    float2 f0 = __half22float2(*(__half2*)&v.x);
    float2 f1 = __half22float2(*(__half2*)&v.y);
    float2 f2 = __half22float2(*(__half2*)&v.z);
    float2 f3 = __half22float2(*(__half2*)&v.w);
    a[0].x += f0.x; a[0].y += f0.y;
    a[1].x += f1.x; a[1].y += f1.y;
    a[2].x += f2.x; a[2].y += f2.y;
    a[3].x += f3.x; a[3].y += f3.y;
}

// -------- CSR build --------
__global__ void init_kernel() {
    int i = blockIdx.x * blockDim.x + threadIdx.x;
    if (i < N) g_deg[i] = 0;
    if (i < G) g_gcnt[i] = 0;
}
__global__ void count_kernel(const int* __restrict__ ei, const int* __restrict__ batch) {
    int i = blockIdx.x * blockDim.x + threadIdx.x;
    int stride = gridDim.x * blockDim.x;
    for (int t = i; t < E + N; t += stride) {
        if (t < E) atomicAdd(&g_deg[ei[E + t]], 1);
        else       atomicAdd(&g_gcnt[batch[t - E]], 1);
    }
}
__global__ void scan_kernel() {
    __shared__ int part[1024];
    int tid = threadIdx.x;
    const int CH = (N + 1023) / 1024;
    int base = tid * CH;
    int s = 0;
    for (int q = 0; q < CH; q++) { int idx = base + q; if (idx < N) s += g_deg[idx]; }
    part[tid] = s;
    __syncthreads();
    for (int off = 1; off < 1024; off <<= 1) {
        int v = (tid >= off) ? part[tid - off] : 0;
        __syncthreads();
        part[tid] += v;
        __syncthreads();
    }
    int run = (tid == 0) ? 0 : part[tid - 1];
    for (int q = 0; q < CH; q++) {
        int idx = base + q;
        if (idx < N) { g_rowptr[idx] = run; g_cursor[idx] = run; run += g_deg[idx]; }
    }
    if (tid == 1023) g_rowptr[N] = run;
}
__global__ void fill_kernel(const int* __restrict__ ei) {
    int i = blockIdx.x * blockDim.x + threadIdx.x;
    int stride = gridDim.x * blockDim.x;
    for (int e = i; e < E; e += stride) {
        int dst = ei[E + e];
        int pos = atomicAdd(&g_cursor[dst], 1);
        g_cols[pos] = ei[e];
    }
}

// ================= fused layer kernel (both signs per CTA, fp16 h storage) =================
// MODE 0: x -> g_h0            (rank-1 W1 + relu, tensor GEMM with W2; both signs)
// MODE 1: g_h0 -> g_h1         (gather + W1 + relu + W2; both signs)
// MODE 2: g_h1 -> g_acc        (gather + MLP + masked-K reduce over k AND signs)
// Warp w <-> (nl = w>>1, sign = w&1) owns rows w*16..w*16+15.
template <int MODE>
__global__ __launch_bounds__(NT, 2) void layer_mma(
    const float* __restrict__ x,
    const float* __restrict__ W1, const float* __restrict__ b1,
    const float* __restrict__ W2, const float* __restrict__ b2,
    const int* __restrict__ batch)
{
    extern __shared__ float dyn[];
    float* sS = dyn;                    // 256 * AS
    float* sW = dyn + 256 * AS;         // 64 * WS
    float* sk = sW + 64 * WS;           // 128

    int tid = threadIdx.x, w = tid >> 5, l = tid & 31;
    int base = blockIdx.x * NPB;

    stage_w(sW, (MODE == 0) ? W2 : W1, tid);

    if (MODE == 0) {
        if (tid < 128) {
            int nl = tid >> 4, k = tid & 15;
            int i = base + nl;
            float s = x[i * K + k];
            int rp = g_rowptr[i], re = g_rowptr[i + 1];
            for (int e = rp; e < re; e++) s += x[__ldg(g_cols + e) * K + k];
            sk[tid] = s;
        }
        __syncthreads();
        // A[r][c] = tf32(relu(+/-s * W1[c] + b1[c])); 2 threads per row, 32 cols each
        int r = tid >> 1, c0 = (tid & 1) * 32;
        int nl = r >> 5, sgn = (r >> 4) & 1, k = r & 15;
        float sv = sk[nl * 16 + k];
        if (sgn) sv = -sv;
#pragma unroll
        for (int q = 0; q < 8; q++) {
            float4 wv = __ldg((const float4*)(W1 + c0) + q);
            float4 bv = __ldg((const float4*)(b1 + c0) + q);
            float4 t;
            t.x = tf32r(fmaxf(fmaf(sv, wv.x, bv.x), 0.f));
            t.y = tf32r(fmaxf(fmaf(sv, wv.y, bv.y), 0.f));
            t.z = tf32r(fmaxf(fmaf(sv, wv.z, bv.z), 0.f));
            t.w = tf32r(fmaxf(fmaf(sv, wv.w, bv.w), 0.f));
            *(float4*)(sS + r * AS + c0 + q * 4) = t;
        }
    } else {
        // gather: warp w -> (node, sign). fp16 h, fp32 accumulation; edge unroll x2.
        int i = base + (w >> 1), sgn = w & 1;
        const uint4* h4 = (const uint4*)((MODE == 1) ? g_h0 : g_h1);  // 128 uint4 per (node,sign)
        const uint4* self = h4 + ((size_t)i * 2 + sgn) * 128;
        float2 a[16];
#pragma unroll
        for (int q = 0; q < 4; q++) {
            a[q*4].x = 0.f; a[q*4].y = 0.f; a[q*4+1].x = 0.f; a[q*4+1].y = 0.f;
            a[q*4+2].x = 0.f; a[q*4+2].y = 0.f; a[q*4+3].x = 0.f; a[q*4+3].y = 0.f;
            acc8(a + q*4, self[l + 32*q]);
        }
        int rp = g_rowptr[i], re = g_rowptr[i + 1];
        int e = rp;
        for (; e + 1 < re; e += 2) {
            const uint4* p0 = h4 + ((size_t)__ldg(g_cols + e)     * 2 + sgn) * 128;
            const uint4* p1 = h4 + ((size_t)__ldg(g_cols + e + 1) * 2 + sgn) * 128;
            uint4 v0[4], v1[4];
#pragma unroll
            for (int q = 0; q < 4; q++) v0[q] = p0[l + 32*q];
#pragma unroll
            for (int q = 0; q < 4; q++) v1[q] = p1[l + 32*q];
#pragma unroll
            for (int q = 0; q < 4; q++) { acc8(a + q*4, v0[q]); acc8(a + q*4, v1[q]); }
        }
        if (e < re) {
            const uint4* p0 = h4 + ((size_t)__ldg(g_cols + e) * 2 + sgn) * 128;
#pragma unroll
            for (int q = 0; q < 4; q++) acc8(a + q*4, p0[l + 32*q]);
        }
        // stage to sS (tf32-rounded): unit = l+32q covers 8 channels at row k
#pragma unroll
        for (int q = 0; q < 4; q++) {
            int unit = l + 32*q;
            int k = unit >> 3, c0 = (unit & 7) * 8;
            float4 t0, t1;
            t0.x = tf32r(a[q*4+0].x); t0.y = tf32r(a[q*4+0].y);
            t0.z = tf32r(a[q*4+1].x); t0.w = tf32r(a[q*4+1].y);
            t1.x = tf32r(a[q*4+2].x); t1.y = tf32r(a[q*4+2].y);
            t1.z = tf32r(a[q*4+3].x); t1.w = tf32r(a[q*4+3].y);
            *(float4*)(sS + (w * 16 + k) * AS + c0) = t0;
            *(float4*)(sS + (w * 16 + k) * AS + c0 + 4) = t1;
        }
    }
    __syncthreads();

    // ---- GEMM1 ----
    float acc[8][4];
    int r0 = w * 16;
    gemm_mma(sS, sW, r0, l, acc);

    if (MODE == 0) {
        __half* gh = g_h0 + ((size_t)(base + (w >> 1)) * 2 + (w & 1)) * 1024;
        int k = l >> 2;
#pragma unroll
        for (int nt = 0; nt < 8; nt++) {
            int col = nt * 8 + 2 * (l & 3);
            float2 bv = __ldg((const float2*)(b2 + col));
            *(__half2*)(gh + k * 64 + col)       = __floats2half2_rn(acc[nt][0] + bv.x, acc[nt][1] + bv.y);
            *(__half2*)(gh + (k + 8) * 64 + col) = __floats2half2_rn(acc[nt][2] + bv.x, acc[nt][3] + bv.y);
        }
        return;
    }

    __syncthreads();   // all GEMM1 smem reads complete

    // t = tf32(relu(D1 + b1)) back into sS; restage sW = W2
    {
        int rd = r0 + (l >> 2);
#pragma unroll
        for (int nt = 0; nt < 8; nt++) {
            int col = nt * 8 + 2 * (l & 3);
            float2 bv = __ldg((const float2*)(b1 + col));
            float2 v0 = { tf32r(fmaxf(acc[nt][0] + bv.x, 0.f)),
                          tf32r(fmaxf(acc[nt][1] + bv.y, 0.f)) };
            float2 v1 = { tf32r(fmaxf(acc[nt][2] + bv.x, 0.f)),
                          tf32r(fmaxf(acc[nt][3] + bv.y, 0.f)) };
            *(float2*)(sS + rd * AS + col) = v0;
            *(float2*)(sS + (rd + 8) * AS + col) = v1;
        }
    }
    stage_w(sW, W2, tid);
    __syncthreads();

    // ---- GEMM2 ----
    gemm_mma(sS, sW, r0, l, acc);

    if (MODE == 1) {
        __half* gh = g_h1 + ((size_t)(base + (w >> 1)) * 2 + (w & 1)) * 1024;
        int k = l >> 2;
#pragma unroll
        for (int nt = 0; nt < 8; nt++) {
            int col = nt * 8 + 2 * (l & 3);
            float2 bv = __ldg((const float2*)(b2 + col));
            *(__half2*)(gh + k * 64 + col)       = __floats2half2_rn(acc[nt][0] + bv.x, acc[nt][1] + bv.y);
            *(__half2*)(gh + (k + 8) * 64 + col) = __floats2half2_rn(acc[nt][2] + bv.x, acc[nt][3] + bv.y);
        }
    } else {
        // MODE 2: stage D2 + b2 into sS; masked reduce over signs and k; store g_acc
        __syncthreads();   // all GEMM2 smem reads complete before overwrite
        {
            int rd = r0 + (l >> 2);
#pragma unroll
            for (int nt = 0; nt < 8; nt++) {
                int col = nt * 8 + 2 * (l & 3);
                float2 bv = __ldg((const float2*)(b2 + col));
                float2 v0 = { acc[nt][0] + bv.x, acc[nt][1] + bv.y };
                float2 v1 = { acc[nt][2] + bv.x, acc[nt][3] + bv.y };
                *(float2*)(sS + rd * AS + col) = v0;
                *(float2*)(sS + (rd + 8) * AS + col) = v1;
            }
        }
        __syncthreads();
        int nl = tid >> 6, c = tid & 63;   // 8 nodes x 64 channels
        int i2 = base + nl;
        int nn = g_gcnt[batch[i2]];
        if (nn > 16) nn = 16;
        float s = 0.f;
#pragma unroll 2
        for (int sg = 0; sg < 2; sg++)
            for (int k2 = 0; k2 < nn; k2++)
                s += sS[((nl * 2 + sg) * 16 + k2) * AS + c];
        g_acc[(size_t)i2 * 64 + c] = s;
    }
}

// -------- rho MLP: g_acc [N,64] -> out [N,16] --------
__global__ __launch_bounds__(256) void rho_kernel(
    const float* __restrict__ rW1, const float* __restrict__ rb1,
    const float* __restrict__ rW2, const float* __restrict__ rb2,
    float* __restrict__ out) {
    __shared__ float v[4][64];
    __shared__ float t[4][64];
    int tid = threadIdx.x;
    int nl = tid >> 6, c = tid & 63;
    int i = blockIdx.x * 4 + nl;
    v[nl][c] = g_acc[(size_t)i * 64 + c];
    __syncthreads();
    float s = rb1[c];
#pragma unroll 4
    for (int k = 0; k < 64; k++) s += v[nl][k] * rW1[k * 64 + c];
    t[nl][c] = fmaxf(s, 0.f);
    __syncthreads();
    if (c < 16) {
        float o = rb2[c];
#pragma unroll 4
        for (int k = 0; k < 64; k++) o += t[nl][k] * rW2[k * 16 + c];
        out[i * 16 + c] = o;
    }
}

// -------- launch --------
extern "C" void kernel_launch(void* const* d_in, const int* in_sizes, int n_in,
                              void* d_out, int out_size) {
    (void)in_sizes; (void)n_in; (void)out_size;
    const float* x     = (const float*)d_in[0];
    const int*   ei    = (const int*)d_in[1];
    const int*   batch = (const int*)d_in[2];
    const float* gW1[3] = {(const float*)d_in[3], (const float*)d_in[7],  (const float*)d_in[11]};
    const float* gb1[3] = {(const float*)d_in[4], (const float*)d_in[8],  (const float*)d_in[12]};
    const float* gW2[3] = {(const float*)d_in[5], (const float*)d_in[9],  (const float*)d_in[13]};
    const float* gb2[3] = {(const float*)d_in[6], (const float*)d_in[10], (const float*)d_in[14]};
    const float* rW1 = (const float*)d_in[15];
    const float* rb1 = (const float*)d_in[16];
    const float* rW2 = (const float*)d_in[17];
    const float* rb2 = (const float*)d_in[18];

    const int SMEMSZ = (256 * AS + 64 * WS + 128) * 4;   // 88576 bytes
    cudaFuncSetAttribute(layer_mma<0>, cudaFuncAttributeMaxDynamicSharedMemorySize, SMEMSZ);
    cudaFuncSetAttribute(layer_mma<1>, cudaFuncAttributeMaxDynamicSharedMemorySize, SMEMSZ);
    cudaFuncSetAttribute(layer_mma<2>, cudaFuncAttributeMaxDynamicSharedMemorySize, SMEMSZ);

    init_kernel<<<(N + 255) / 256, 256>>>();
    count_kernel<<<160, 256>>>(ei, batch);
    scan_kernel<<<1, 1024>>>();
    fill_kernel<<<160, 256>>>(ei);

    layer_mma<0><<<BLKS, NT, SMEMSZ>>>(x, gW1[0], gb1[0], gW2[0], gb2[0], batch);
    layer_mma<1><<<BLKS, NT, SMEMSZ>>>(x, gW1[1], gb1[1], gW2[1], gb2[1], batch);
    layer_mma<2><<<BLKS, NT, SMEMSZ>>>(x, gW1[2], gb1[2], gW2[2], gb2[2], batch);

    rho_kernel<<<N / 4, 256>>>(rW1, rb1, rW2, rb2, (float*)d_out);
}

// round 12
// speedup vs baseline: 3.3127x; 1.1197x over previous
#include <cuda_runtime.h>
#include <cuda_fp16.h>
#include <cstdint>

// Problem constants
constexpr int N  = 20000;
constexpr int K  = 16;
constexpr int E  = 160000;
constexpr int G  = 100;
constexpr int NPB  = 8;            // nodes per block (x2 signs x16 k = 256 MMA rows)
constexpr int BLKS = N / NPB;      // 2500
constexpr int NT   = 512;          // threads per CTA (16 warps)
constexpr int AS = 68;             // sS row stride (floats) — A-frag conflict-free
constexpr int WS = 72;             // sW row stride (floats) — B-frag conflict-free

// h1 layout: [node][sign][k][c]; 1024 halves per (node,sign)
__device__ __align__(16) __half g_h1[(size_t)N * 2 * 1024];
__device__ __align__(16) float  g_s[(size_t)N * K];     // aggregated scalars x + sum(x_nbrs)
__device__ __align__(16) float  g_acc[(size_t)N * 64];
__device__ int g_deg[N];
__device__ int g_rowptr[N + 1];
__device__ int g_cursor[N];
__device__ int g_cols[E];
__device__ int g_gcnt[G];

// ================= helpers =================
__device__ __forceinline__ float tf32r(float a) {
    uint32_t u; asm("cvt.rna.tf32.f32 %0, %1;" : "=r"(u) : "f"(a));
    return __uint_as_float(u);
}

__device__ __forceinline__ void mma8(float d[4], uint32_t a0, uint32_t a1,
                                     uint32_t a2, uint32_t a3,
                                     uint32_t b0, uint32_t b1) {
    asm volatile(
        "mma.sync.aligned.m16n8k8.row.col.f32.tf32.tf32.f32 "
        "{%0,%1,%2,%3}, {%4,%5,%6,%7}, {%8,%9}, {%0,%1,%2,%3};"
        : "+f"(d[0]), "+f"(d[1]), "+f"(d[2]), "+f"(d[3])
        : "r"(a0), "r"(a1), "r"(a2), "r"(a3), "r"(b0), "r"(b1));
}

// Warp GEMM: rows r0..r0+15 (M=16), cols 0..63 (8 n-tiles), K=64.
__device__ __forceinline__ void gemm_mma(const float* __restrict__ sS,
                                         const float* __restrict__ sW,
                                         int r0, int l, float acc[8][4]) {
#pragma unroll
    for (int nt = 0; nt < 8; nt++)
#pragma unroll
        for (int j = 0; j < 4; j++) acc[nt][j] = 0.f;
    int ar = r0 + (l >> 2);
    int ac = l & 3;
    int nr = l >> 2;
#pragma unroll
    for (int ks = 0; ks < 8; ks++) {
        int k0 = ks * 8;
        uint32_t a0 = __float_as_uint(sS[ar * AS + k0 + ac]);
        uint32_t a1 = __float_as_uint(sS[(ar + 8) * AS + k0 + ac]);
        uint32_t a2 = __float_as_uint(sS[ar * AS + k0 + ac + 4]);
        uint32_t a3 = __float_as_uint(sS[(ar + 8) * AS + k0 + ac + 4]);
#pragma unroll
        for (int nt = 0; nt < 8; nt++) {
            int n0 = nt * 8 + nr;
            uint32_t b0 = __float_as_uint(sW[(k0 + ac) * WS + n0]);
            uint32_t b1 = __float_as_uint(sW[(k0 + ac + 4) * WS + n0]);
            mma8(acc[nt], a0, a1, a2, a3, b0, b1);
        }
    }
}

__device__ __forceinline__ void stage_w(float* sW, const float* __restrict__ W, int tid) {
    for (int e = tid; e < 1024; e += NT) {
        int k = e >> 4, n4 = (e & 15) * 4;
        float4 v = __ldg((const float4*)(W + k * 64 + n4));
        v.x = tf32r(v.x); v.y = tf32r(v.y); v.z = tf32r(v.z); v.w = tf32r(v.w);
        *(float4*)(sW + k * WS + n4) = v;
    }
}

// accumulate one uint4 (8 halves) into 4 float2 accumulators
__device__ __forceinline__ void acc8(float2* a, uint4 v) {
    float2 f0 = __half22float2(*(__half2*)&v.x);
    float2 f1 = __half22float2(*(__half2*)&v.y);
    float2 f2 = __half22float2(*(__half2*)&v.z);
    float2 f3 = __half22float2(*(__half2*)&v.w);
    a[0].x += f0.x; a[0].y += f0.y;
    a[1].x += f1.x; a[1].y += f1.y;
    a[2].x += f2.x; a[2].y += f2.y;
    a[3].x += f3.x; a[3].y += f3.y;
}

// -------- CSR build --------
__global__ void init_kernel() {
    int i = blockIdx.x * blockDim.x + threadIdx.x;
    if (i < N) g_deg[i] = 0;
    if (i < G) g_gcnt[i] = 0;
}
__global__ void count_kernel(const int* __restrict__ ei, const int* __restrict__ batch) {
    int i = blockIdx.x * blockDim.x + threadIdx.x;
    int stride = gridDim.x * blockDim.x;
    for (int t = i; t < E + N; t += stride) {
        if (t < E) atomicAdd(&g_deg[ei[E + t]], 1);
        else       atomicAdd(&g_gcnt[batch[t - E]], 1);
    }
}
__global__ void scan_kernel() {
    __shared__ int part[1024];
    int tid = threadIdx.x;
    const int CH = (N + 1023) / 1024;
    int base = tid * CH;
    int s = 0;
    for (int q = 0; q < CH; q++) { int idx = base + q; if (idx < N) s += g_deg[idx]; }
    part[tid] = s;
    __syncthreads();
    for (int off = 1; off < 1024; off <<= 1) {
        int v = (tid >= off) ? part[tid - off] : 0;
        __syncthreads();
        part[tid] += v;
        __syncthreads();
    }
    int run = (tid == 0) ? 0 : part[tid - 1];
    for (int q = 0; q < CH; q++) {
        int idx = base + q;
        if (idx < N) { g_rowptr[idx] = run; g_cursor[idx] = run; run += g_deg[idx]; }
    }
    if (tid == 1023) g_rowptr[N] = run;
}
__global__ void fill_kernel(const int* __restrict__ ei) {
    int i = blockIdx.x * blockDim.x + threadIdx.x;
    int stride = gridDim.x * blockDim.x;
    for (int e = i; e < E; e += stride) {
        int dst = ei[E + e];
        int pos = atomicAdd(&g_cursor[dst], 1);
        g_cols[pos] = ei[e];
    }
}

// -------- s = x + sum_{j in N(i)} x_j  (per node, per k) --------
__global__ __launch_bounds__(256) void s_kernel(const float* __restrict__ x) {
    int gid = blockIdx.x * blockDim.x + threadIdx.x;   // gid -> (node, k)
    if (gid >= N * K) return;
    int i = gid >> 4, k = gid & 15;
    float s = x[i * K + k];
    int rp = g_rowptr[i], re = g_rowptr[i + 1];
    for (int e = rp; e < re; e++) s += x[__ldg(g_cols + e) * K + k];
    g_s[gid] = s;
}

// ================= kernel A: fused GIN layers 0+1 (scalar-space gather) =================
// Per warp w = (node nl=w>>1, sign w&1):
//  R[k][c] = sum over {dst} U N(dst) of relu(sgn*s_jk * W1_0[c] + b1_0[c])
//  z  = R @ W2_0 + (1+deg) * b2_0
//  h1 = relu(z @ W1_1 + b1_1) @ W2_1 + b2_1  -> g_h1 (fp16)
__global__ __launch_bounds__(NT, 2) void fusedA(
    const float* __restrict__ W1_0, const float* __restrict__ b1_0,
    const float* __restrict__ W2_0, const float* __restrict__ b2_0,
    const float* __restrict__ W1_1, const float* __restrict__ b1_1,
    const float* __restrict__ W2_1, const float* __restrict__ b2_1)
{
    extern __shared__ float dyn[];
    float* sS = dyn;                    // 256 * AS
    float* sW = dyn + 256 * AS;         // 64 * WS

    int tid = threadIdx.x, w = tid >> 5, l = tid & 31;
    int base = blockIdx.x * NPB;

    stage_w(sW, W2_0, tid);

    // ---- scalar-space gather + rank-1 relu expansion ----
    int i = base + (w >> 1);
    float sgn = (w & 1) ? -1.f : 1.f;
    // lane l owns channels (2l, 2l+1) for all 16 k
    float w1x = sgn * __ldg(W1_0 + 2 * l), w1y = sgn * __ldg(W1_0 + 2 * l + 1);
    float b1x = __ldg(b1_0 + 2 * l),       b1y = __ldg(b1_0 + 2 * l + 1);
    float2 a[16];
#pragma unroll
    for (int k = 0; k < 16; k++) { a[k].x = 0.f; a[k].y = 0.f; }

    int rp = g_rowptr[i], re = g_rowptr[i + 1];
    int deg = re - rp;
    float sv_cur = (l < 16) ? g_s[(size_t)i * 16 + l] : 0.f;   // self term
    for (int t = 0; t <= deg; t++) {
        float sv_next = 0.f;
        if (t < deg) {
            int j = __ldg(g_cols + rp + t);
            if (l < 16) sv_next = g_s[(size_t)j * 16 + l];
        }
#pragma unroll
        for (int k = 0; k < 16; k++) {
            float sk = __shfl_sync(0xffffffffu, sv_cur, k);
            a[k].x += fmaxf(fmaf(sk, w1x, b1x), 0.f);
            a[k].y += fmaxf(fmaf(sk, w1y, b1y), 0.f);
        }
        sv_cur = sv_next;
    }
    // stage R (tf32) into sS: row = w*16+k, cols (2l, 2l+1)
#pragma unroll
    for (int k = 0; k < 16; k++) {
        float2 t2 = { tf32r(a[k].x), tf32r(a[k].y) };
        *(float2*)(sS + (w * 16 + k) * AS + 2 * l) = t2;
    }
    __syncthreads();

    // ---- GEMM1: z = R @ W2_0 ----
    float acc[8][4];
    int r0 = w * 16;
    gemm_mma(sS, sW, r0, l, acc);
    __syncthreads();

    // z + (1+deg)*b2_0 -> tf32 -> sS ; stage W1_1
    {
        float c = (float)(1 + deg);
        int rd = r0 + (l >> 2);
#pragma unroll
        for (int nt = 0; nt < 8; nt++) {
            int col = nt * 8 + 2 * (l & 3);
            float2 bv = __ldg((const float2*)(b2_0 + col));
            float2 v0 = { tf32r(fmaf(c, bv.x, acc[nt][0])), tf32r(fmaf(c, bv.y, acc[nt][1])) };
            float2 v1 = { tf32r(fmaf(c, bv.x, acc[nt][2])), tf32r(fmaf(c, bv.y, acc[nt][3])) };
            *(float2*)(sS + rd * AS + col) = v0;
            *(float2*)(sS + (rd + 8) * AS + col) = v1;
        }
    }
    stage_w(sW, W1_1, tid);
    __syncthreads();

    // ---- GEMM2: t = relu(z @ W1_1 + b1_1) ----
    gemm_mma(sS, sW, r0, l, acc);
    __syncthreads();
    {
        int rd = r0 + (l >> 2);
#pragma unroll
        for (int nt = 0; nt < 8; nt++) {
            int col = nt * 8 + 2 * (l & 3);
            float2 bv = __ldg((const float2*)(b1_1 + col));
            float2 v0 = { tf32r(fmaxf(acc[nt][0] + bv.x, 0.f)),
                          tf32r(fmaxf(acc[nt][1] + bv.y, 0.f)) };
            float2 v1 = { tf32r(fmaxf(acc[nt][2] + bv.x, 0.f)),
                          tf32r(fmaxf(acc[nt][3] + bv.y, 0.f)) };
            *(float2*)(sS + rd * AS + col) = v0;
            *(float2*)(sS + (rd + 8) * AS + col) = v1;
        }
    }
    stage_w(sW, W2_1, tid);
    __syncthreads();

    // ---- GEMM3: h1 = t @ W2_1 + b2_1 -> fp16 ----
    gemm_mma(sS, sW, r0, l, acc);
    {
        __half* gh = g_h1 + ((size_t)(base + (w >> 1)) * 2 + (w & 1)) * 1024;
        int k = l >> 2;
#pragma unroll
        for (int nt = 0; nt < 8; nt++) {
            int col = nt * 8 + 2 * (l & 3);
            float2 bv = __ldg((const float2*)(b2_1 + col));
            *(__half2*)(gh + k * 64 + col)       = __floats2half2_rn(acc[nt][0] + bv.x, acc[nt][1] + bv.y);
            *(__half2*)(gh + (k + 8) * 64 + col) = __floats2half2_rn(acc[nt][2] + bv.x, acc[nt][3] + bv.y);
        }
    }
}

// ================= kernel B: layer 2 (gather h1 + MLP + masked reduce) =================
__global__ __launch_bounds__(NT, 2) void layerB(
    const float* __restrict__ W1, const float* __restrict__ b1,
    const float* __restrict__ W2, const float* __restrict__ b2,
    const int* __restrict__ batch)
{
    extern __shared__ float dyn[];
    float* sS = dyn;
    float* sW = dyn + 256 * AS;

    int tid = threadIdx.x, w = tid >> 5, l = tid & 31;
    int base = blockIdx.x * NPB;

    stage_w(sW, W1, tid);

    // gather: warp w -> (node, sign). fp16 h1, fp32 accumulation; edge unroll x2.
    {
        int i = base + (w >> 1), sgn = w & 1;
        const uint4* h4 = (const uint4*)g_h1;
        const uint4* self = h4 + ((size_t)i * 2 + sgn) * 128;
        float2 a[16];
#pragma unroll
        for (int q = 0; q < 4; q++) {
            a[q*4].x = 0.f; a[q*4].y = 0.f; a[q*4+1].x = 0.f; a[q*4+1].y = 0.f;
            a[q*4+2].x = 0.f; a[q*4+2].y = 0.f; a[q*4+3].x = 0.f; a[q*4+3].y = 0.f;
            acc8(a + q*4, self[l + 32*q]);
        }
        int rp = g_rowptr[i], re = g_rowptr[i + 1];
        int e = rp;
        for (; e + 1 < re; e += 2) {
            const uint4* p0 = h4 + ((size_t)__ldg(g_cols + e)     * 2 + sgn) * 128;
            const uint4* p1 = h4 + ((size_t)__ldg(g_cols + e + 1) * 2 + sgn) * 128;
            uint4 v0[4], v1[4];
#pragma unroll
            for (int q = 0; q < 4; q++) v0[q] = p0[l + 32*q];
#pragma unroll
            for (int q = 0; q < 4; q++) v1[q] = p1[l + 32*q];
#pragma unroll
            for (int q = 0; q < 4; q++) { acc8(a + q*4, v0[q]); acc8(a + q*4, v1[q]); }
        }
        if (e < re) {
            const uint4* p0 = h4 + ((size_t)__ldg(g_cols + e) * 2 + sgn) * 128;
#pragma unroll
            for (int q = 0; q < 4; q++) acc8(a + q*4, p0[l + 32*q]);
        }
#pragma unroll
        for (int q = 0; q < 4; q++) {
            int unit = l + 32*q;
            int k = unit >> 3, c0 = (unit & 7) * 8;
            float4 t0, t1;
            t0.x = tf32r(a[q*4+0].x); t0.y = tf32r(a[q*4+0].y);
            t0.z = tf32r(a[q*4+1].x); t0.w = tf32r(a[q*4+1].y);
            t1.x = tf32r(a[q*4+2].x); t1.y = tf32r(a[q*4+2].y);
            t1.z = tf32r(a[q*4+3].x); t1.w = tf32r(a[q*4+3].y);
            *(float4*)(sS + (w * 16 + k) * AS + c0) = t0;
            *(float4*)(sS + (w * 16 + k) * AS + c0 + 4) = t1;
        }
    }
    __syncthreads();

    float acc[8][4];
    int r0 = w * 16;
    gemm_mma(sS, sW, r0, l, acc);
    __syncthreads();

    {
        int rd = r0 + (l >> 2);
#pragma unroll
        for (int nt = 0; nt < 8; nt++) {
            int col = nt * 8 + 2 * (l & 3);
            float2 bv = __ldg((const float2*)(b1 + col));
            float2 v0 = { tf32r(fmaxf(acc[nt][0] + bv.x, 0.f)),
                          tf32r(fmaxf(acc[nt][1] + bv.y, 0.f)) };
            float2 v1 = { tf32r(fmaxf(acc[nt][2] + bv.x, 0.f)),
                          tf32r(fmaxf(acc[nt][3] + bv.y, 0.f)) };
            *(float2*)(sS + rd * AS + col) = v0;
            *(float2*)(sS + (rd + 8) * AS + col) = v1;
        }
    }
    stage_w(sW, W2, tid);
    __syncthreads();

    gemm_mma(sS, sW, r0, l, acc);
    __syncthreads();   // all GEMM2 smem reads complete before overwrite
    {
        int rd = r0 + (l >> 2);
#pragma unroll
        for (int nt = 0; nt < 8; nt++) {
            int col = nt * 8 + 2 * (l & 3);
            float2 bv = __ldg((const float2*)(b2 + col));
            float2 v0 = { acc[nt][0] + bv.x, acc[nt][1] + bv.y };
            float2 v1 = { acc[nt][2] + bv.x, acc[nt][3] + bv.y };
            *(float2*)(sS + rd * AS + col) = v0;
            *(float2*)(sS + (rd + 8) * AS + col) = v1;
        }
    }
    __syncthreads();
    int nl = tid >> 6, c = tid & 63;   // 8 nodes x 64 channels
    int i2 = base + nl;
    int nn = g_gcnt[batch[i2]];
    if (nn > 16) nn = 16;
    float s = 0.f;
#pragma unroll 2
    for (int sg = 0; sg < 2; sg++)
        for (int k2 = 0; k2 < nn; k2++)
            s += sS[((nl * 2 + sg) * 16 + k2) * AS + c];
    g_acc[(size_t)i2 * 64 + c] = s;
}

// -------- rho MLP: g_acc [N,64] -> out [N,16] --------
__global__ __launch_bounds__(256) void rho_kernel(
    const float* __restrict__ rW1, const float* __restrict__ rb1,
    const float* __restrict__ rW2, const float* __restrict__ rb2,
    float* __restrict__ out) {
    __shared__ float v[4][64];
    __shared__ float t[4][64];
    int tid = threadIdx.x;
    int nl = tid >> 6, c = tid & 63;
    int i = blockIdx.x * 4 + nl;
    v[nl][c] = g_acc[(size_t)i * 64 + c];
    __syncthreads();
    float s = rb1[c];
#pragma unroll 4
    for (int k = 0; k < 64; k++) s += v[nl][k] * rW1[k * 64 + c];
    t[nl][c] = fmaxf(s, 0.f);
    __syncthreads();
    if (c < 16) {
        float o = rb2[c];
#pragma unroll 4
        for (int k = 0; k < 64; k++) o += t[nl][k] * rW2[k * 16 + c];
        out[i * 16 + c] = o;
    }
}

// -------- launch --------
extern "C" void kernel_launch(void* const* d_in, const int* in_sizes, int n_in,
                              void* d_out, int out_size) {
    (void)in_sizes; (void)n_in; (void)out_size;
    const float* x     = (const float*)d_in[0];
    const int*   ei    = (const int*)d_in[1];
    const int*   batch = (const int*)d_in[2];
    const float* gW1[3] = {(const float*)d_in[3], (const float*)d_in[7],  (const float*)d_in[11]};
    const float* gb1[3] = {(const float*)d_in[4], (const float*)d_in[8],  (const float*)d_in[12]};
    const float* gW2[3] = {(const float*)d_in[5], (const float*)d_in[9],  (const float*)d_in[13]};
    const float* gb2[3] = {(const float*)d_in[6], (const float*)d_in[10], (const float*)d_in[14]};
    const float* rW1 = (const float*)d_in[15];
    const float* rb1 = (const float*)d_in[16];
    const float* rW2 = (const float*)d_in[17];
    const float* rb2 = (const float*)d_in[18];

    const int SMEMSZ = (256 * AS + 64 * WS) * 4;   // 88064 bytes
    cudaFuncSetAttribute(fusedA, cudaFuncAttributeMaxDynamicSharedMemorySize, SMEMSZ);
    cudaFuncSetAttribute(layerB, cudaFuncAttributeMaxDynamicSharedMemorySize, SMEMSZ);

    init_kernel<<<(N + 255) / 256, 256>>>();
    count_kernel<<<160, 256>>>(ei, batch);
    scan_kernel<<<1, 1024>>>();
    fill_kernel<<<160, 256>>>(ei);
    s_kernel<<<(N * K + 255) / 256, 256>>>(x);

    fusedA<<<BLKS, NT, SMEMSZ>>>(gW1[0], gb1[0], gW2[0], gb2[0],
                                 gW1[1], gb1[1], gW2[1], gb2[1]);
    layerB<<<BLKS, NT, SMEMSZ>>>(gW1[2], gb1[2], gW2[2], gb2[2], batch);

    rho_kernel<<<N / 4, 256>>>(rW1, rb1, rW2, rb2, (float*)d_out);
}